// round 1
// baseline (speedup 1.0000x reference)
#include <cuda_runtime.h>
#include <mma.h>
#include <cstdint>

using namespace nvcuda;

#define TOK    262144          // 4*256*256 tokens
#define CDIM   192

// ---------------- scratch (device globals; no allocation) ----------------
__device__ float g_ln  [(size_t)TOK * 192];   // LN1 (window layout) then LN2 (token layout)
__device__ float g_big [(size_t)TOK * 768];   // qkv (576 wide) then fc1 activation (768 wide)
__device__ float g_ow  [(size_t)TOK * 192];   // attention output, window layout
__device__ float g_xo  [(size_t)TOK * 192];   // post-attention residual, token layout

// ---------------- LayerNorm (one warp per token) ----------------
// WINDOW_DST: write rows permuted into window order (B*nW, 64, C)
template<bool WINDOW_DST>
__global__ __launch_bounds__(256) void ln_kernel(const float* __restrict__ x,
                                                 const float* __restrict__ g,
                                                 const float* __restrict__ b,
                                                 float* __restrict__ out)
{
    int tok  = blockIdx.x * (blockDim.x >> 5) + (threadIdx.x >> 5);
    int lane = threadIdx.x & 31;
    const float* row = x + (size_t)tok * CDIM;
    float v[6];
    float s = 0.f, s2 = 0.f;
#pragma unroll
    for (int k = 0; k < 6; k++) {
        v[k] = row[lane + 32 * k];
        s  += v[k];
        s2 += v[k] * v[k];
    }
#pragma unroll
    for (int o = 16; o > 0; o >>= 1) {
        s  += __shfl_xor_sync(0xffffffffu, s,  o);
        s2 += __shfl_xor_sync(0xffffffffu, s2, o);
    }
    float mean = s * (1.f / 192.f);
    float var  = s2 * (1.f / 192.f) - mean * mean;
    float inv  = rsqrtf(var + 1e-5f);

    size_t drow;
    if (WINDOW_DST) {
        int bb  = tok >> 16;
        int rem = tok & 65535;
        int h   = rem >> 8;
        int w   = rem & 255;
        int win = (bb << 10) + ((h >> 3) << 5) + (w >> 3);
        int n   = ((h & 7) << 3) + (w & 7);
        drow = (size_t)win * 64 + n;
    } else {
        drow = (size_t)tok;
    }
    float* orow = out + drow * CDIM;
#pragma unroll
    for (int k = 0; k < 6; k++) {
        int c = lane + 32 * k;
        orow[c] = (v[k] - mean) * inv * g[c] + b[c];
    }
}

// ---------------- GEMM: tf32 wmma, 128x64 block tile, BK=32 ----------------
#define BM 128
#define BN 64
#define BK 32

enum { EPI_QKV = 0, EPI_PROJ = 1, EPI_FC1 = 2, EPI_FC2 = 3 };

template<int KDIM, int NDIM, int EPI>
__global__ __launch_bounds__(256) void gemm_kernel(const float* __restrict__ A,
                                                   const float* __restrict__ B,
                                                   const float* __restrict__ bias,
                                                   const float* __restrict__ res,
                                                   float* __restrict__ out)
{
    __shared__ union {
        struct { float a[BM][BK + 4]; float b[BK][BN + 4]; } ab;
        float c[BM][BN + 4];
    } sm;

    const int bn   = blockIdx.x;
    const int bm   = blockIdx.y;
    const int tid  = threadIdx.x;
    const int warp = tid >> 5;
    const int wrow = warp & 1;   // 0..1 : 64-row group
    const int wcol = warp >> 1;  // 0..3 : 16-col group

    wmma::fragment<wmma::accumulator, 16, 16, 8, float> acc[4];
#pragma unroll
    for (int i = 0; i < 4; i++) wmma::fill_fragment(acc[i], 0.f);

    for (int k0 = 0; k0 < KDIM; k0 += BK) {
        // A tile: 128 x 32 floats = 1024 float4 (4 per thread)
#pragma unroll
        for (int t = 0; t < 4; t++) {
            int idx = tid + t * 256;
            int r = idx >> 3, c4 = idx & 7;
            float4 val = *(const float4*)(A + (size_t)(bm * BM + r) * KDIM + k0 + c4 * 4);
            *(float4*)&sm.ab.a[r][c4 * 4] = val;
        }
        // B tile: 32 x 64 floats = 512 float4 (2 per thread)
#pragma unroll
        for (int t = 0; t < 2; t++) {
            int idx = tid + t * 256;
            int r = idx >> 4, c4 = idx & 15;
            float4 val = *(const float4*)(B + (size_t)(k0 + r) * NDIM + bn * BN + c4 * 4);
            *(float4*)&sm.ab.b[r][c4 * 4] = val;
        }
        __syncthreads();

#pragma unroll
        for (int kk = 0; kk < BK; kk += 8) {
            wmma::fragment<wmma::matrix_b, 16, 16, 8, wmma::precision::tf32, wmma::row_major> bf;
            wmma::load_matrix_sync(bf, &sm.ab.b[kk][wcol * 16], BN + 4);
#pragma unroll
            for (int t = 0; t < bf.num_elements; t++) bf.x[t] = wmma::__float_to_tf32(bf.x[t]);
#pragma unroll
            for (int i = 0; i < 4; i++) {
                wmma::fragment<wmma::matrix_a, 16, 16, 8, wmma::precision::tf32, wmma::row_major> af;
                wmma::load_matrix_sync(af, &sm.ab.a[wrow * 64 + i * 16][kk], BK + 4);
#pragma unroll
                for (int t = 0; t < af.num_elements; t++) af.x[t] = wmma::__float_to_tf32(af.x[t]);
                wmma::mma_sync(acc[i], af, bf, acc[i]);
            }
        }
        __syncthreads();
    }

    // accumulators -> smem C tile
#pragma unroll
    for (int i = 0; i < 4; i++)
        wmma::store_matrix_sync(&sm.c[wrow * 64 + i * 16][wcol * 16], acc[i], BN + 4,
                                wmma::mem_row_major);
    __syncthreads();

    // epilogue (coalesced: each warp handles contiguous half-rows)
    for (int e = tid; e < BM * BN; e += 256) {
        int r = e >> 6, cc = e & 63;
        int gcol = bn * BN + cc;
        size_t grow = (size_t)bm * BM + r;
        float val = sm.c[r][cc] + bias[gcol];

        if constexpr (EPI == EPI_QKV) {
            out[grow * NDIM + gcol] = val;
        } else if constexpr (EPI == EPI_PROJ) {
            // rows are window-ordered; scatter to token order + residual x
            int rg  = (int)grow;
            int win = rg >> 6, n = rg & 63;
            int bb  = win >> 10, wr = win & 1023;
            int h   = ((wr >> 5) << 3) + (n >> 3);
            int w   = ((wr & 31) << 3) + (n & 7);
            size_t t = ((size_t)bb << 16) + ((size_t)h << 8) + (size_t)w;
            val += res[t * CDIM + gcol];
            out[t * CDIM + gcol] = val;
        } else if constexpr (EPI == EPI_FC1) {
            val = val * normcdff(val);            // exact GELU: x * Phi(x)
            out[grow * NDIM + gcol] = val;
        } else {                                  // EPI_FC2
            val += res[grow * (size_t)CDIM + gcol];
            out[grow * (size_t)NDIM + gcol] = val;
        }
    }
}

// ---------------- attention: one block per (window, head), fp32 ----------------
__global__ __launch_bounds__(128) void attn_kernel(const float* __restrict__ qkv,
                                                   float* __restrict__ o)
{
    __shared__ float qs[64][36];
    __shared__ float ks[64][32];
    __shared__ float vs[64][32];
    __shared__ float ps[64][68];

    const int head = blockIdx.x;     // 0..5
    const int win  = blockIdx.y;     // 0..4095
    const int tid  = threadIdx.x;

    const float* base = qkv + (size_t)win * 64 * 576 + head * 32;

    // load q,k,v tiles: 64x32 each, float4-vectorized
#pragma unroll
    for (int t = 0; t < 4; t++) {
        int idx = tid + t * 128;             // 0..511
        int r = idx >> 3, c4 = idx & 7;
        const float* rp = base + (size_t)r * 576;
        *(float4*)&qs[r][c4 * 4] = *(const float4*)(rp +       c4 * 4);
        *(float4*)&ks[r][c4 * 4] = *(const float4*)(rp + 192 + c4 * 4);
        *(float4*)&vs[r][c4 * 4] = *(const float4*)(rp + 384 + c4 * 4);
    }
    __syncthreads();

    const int i    = tid >> 1;    // row 0..63 (2 threads per row)
    const int half = tid & 1;
    const int j0   = half * 32;

    float qr[32];
#pragma unroll
    for (int c4 = 0; c4 < 8; c4++)
        *(float4*)&qr[c4 * 4] = *(float4*)&qs[i][c4 * 4];

    // S[i][j0..j0+31] = scale * q[i] . k[j]
    float sv[32];
#pragma unroll
    for (int jj = 0; jj < 32; jj++) {
        int j = j0 + jj;
        float a = 0.f;
#pragma unroll
        for (int c4 = 0; c4 < 8; c4++) {
            float4 kv = *(float4*)&ks[j][c4 * 4];
            a += qr[c4 * 4 + 0] * kv.x;
            a += qr[c4 * 4 + 1] * kv.y;
            a += qr[c4 * 4 + 2] * kv.z;
            a += qr[c4 * 4 + 3] * kv.w;
        }
        sv[jj] = a * 0.17677669529663687f;   // 1/sqrt(32)
    }

    // softmax over the row (pair of adjacent lanes shares a row)
    float m = -1e30f;
#pragma unroll
    for (int jj = 0; jj < 32; jj++) m = fmaxf(m, sv[jj]);
    m = fmaxf(m, __shfl_xor_sync(0xffffffffu, m, 1));
    float sum = 0.f;
#pragma unroll
    for (int jj = 0; jj < 32; jj++) { sv[jj] = __expf(sv[jj] - m); sum += sv[jj]; }
    sum += __shfl_xor_sync(0xffffffffu, sum, 1);
    float rinv = 1.f / sum;
#pragma unroll
    for (int c4 = 0; c4 < 8; c4++) {
        float4 p = make_float4(sv[c4 * 4] * rinv, sv[c4 * 4 + 1] * rinv,
                               sv[c4 * 4 + 2] * rinv, sv[c4 * 4 + 3] * rinv);
        *(float4*)&ps[i][j0 + c4 * 4] = p;
    }
    __syncwarp();   // row pair is within one warp; vs already block-synced

    // O[i][d0..d0+15] = sum_j P[i][j] * V[j][d]
    float oacc[16];
#pragma unroll
    for (int t = 0; t < 16; t++) oacc[t] = 0.f;
#pragma unroll
    for (int j = 0; j < 64; j++) {
        float p = ps[i][j];
#pragma unroll
        for (int c4 = 0; c4 < 4; c4++) {
            float4 vv = *(float4*)&vs[j][half * 16 + c4 * 4];
            oacc[c4 * 4 + 0] += p * vv.x;
            oacc[c4 * 4 + 1] += p * vv.y;
            oacc[c4 * 4 + 2] += p * vv.z;
            oacc[c4 * 4 + 3] += p * vv.w;
        }
    }
    float* orow = o + (size_t)(win * 64 + i) * CDIM + head * 32 + half * 16;
#pragma unroll
    for (int c4 = 0; c4 < 4; c4++)
        *(float4*)&orow[c4 * 4] = make_float4(oacc[c4 * 4], oacc[c4 * 4 + 1],
                                              oacc[c4 * 4 + 2], oacc[c4 * 4 + 3]);
}

// ---------------- launch ----------------
extern "C" void kernel_launch(void* const* d_in, const int* in_sizes, int n_in,
                              void* d_out, int out_size)
{
    (void)in_sizes; (void)n_in; (void)out_size;
    const float* x      = (const float*)d_in[0];
    const float* g1     = (const float*)d_in[1];
    const float* b1     = (const float*)d_in[2];
    const float* w_qkv  = (const float*)d_in[3];
    const float* b_qkv  = (const float*)d_in[4];
    const float* w_proj = (const float*)d_in[5];
    const float* b_proj = (const float*)d_in[6];
    const float* g2     = (const float*)d_in[7];
    const float* b2     = (const float*)d_in[8];
    const float* w_fc1  = (const float*)d_in[9];
    const float* b_fc1  = (const float*)d_in[10];
    const float* w_fc2  = (const float*)d_in[11];
    const float* b_fc2  = (const float*)d_in[12];
    float* out = (float*)d_out;

    float *ln, *big, *ow, *xo;
    cudaGetSymbolAddress((void**)&ln,  g_ln);
    cudaGetSymbolAddress((void**)&big, g_big);
    cudaGetSymbolAddress((void**)&ow,  g_ow);
    cudaGetSymbolAddress((void**)&xo,  g_xo);

    // 1. LN1 + window partition
    ln_kernel<true><<<TOK / 8, 256>>>(x, g1, b1, ln);
    // 2. QKV GEMM (window-ordered rows)
    gemm_kernel<192, 576, EPI_QKV><<<dim3(9, TOK / BM), 256>>>(ln, w_qkv, b_qkv, nullptr, big);
    // 3. attention per (window, head)
    attn_kernel<<<dim3(6, 4096), 128>>>(big, ow);
    // 4. proj GEMM + window unpartition + residual x  -> xo (token order)
    gemm_kernel<192, 192, EPI_PROJ><<<dim3(3, TOK / BM), 256>>>(ow, w_proj, b_proj, x, xo);
    // 5. LN2 (token order)
    ln_kernel<false><<<TOK / 8, 256>>>(xo, g2, b2, ln);
    // 6. FC1 GEMM + exact GELU
    gemm_kernel<192, 768, EPI_FC1><<<dim3(12, TOK / BM), 256>>>(ln, w_fc1, b_fc1, nullptr, big);
    // 7. FC2 GEMM + residual xo -> out
    gemm_kernel<768, 192, EPI_FC2><<<dim3(3, TOK / BM), 256>>>(big, w_fc2, b_fc2, xo, out);
}

// round 2
// speedup vs baseline: 1.4112x; 1.4112x over previous
#include <cuda_runtime.h>
#include <mma.h>
#include <cstdint>

using namespace nvcuda;

#define TOK    262144          // 4*256*256 tokens
#define CDIM   192

// ---------------- scratch (device globals; no allocation) ----------------
__device__ float g_ln  [(size_t)TOK * 192];   // LN1 (window layout) then LN2 (token layout)
__device__ float g_big [(size_t)TOK * 768];   // qkv (576 wide) then fc1 activation (768 wide)
__device__ float g_ow  [(size_t)TOK * 192];   // attention output, window layout
__device__ float g_xo  [(size_t)TOK * 192];   // post-attention residual, token layout

// ---------------- LayerNorm (one warp per token) ----------------
template<bool WINDOW_DST>
__global__ __launch_bounds__(256) void ln_kernel(const float* __restrict__ x,
                                                 const float* __restrict__ g,
                                                 const float* __restrict__ b,
                                                 float* __restrict__ out)
{
    int tok  = blockIdx.x * (blockDim.x >> 5) + (threadIdx.x >> 5);
    int lane = threadIdx.x & 31;
    const float* row = x + (size_t)tok * CDIM;
    float v[6];
    float s = 0.f, s2 = 0.f;
#pragma unroll
    for (int k = 0; k < 6; k++) {
        v[k] = row[lane + 32 * k];
        s  += v[k];
        s2 += v[k] * v[k];
    }
#pragma unroll
    for (int o = 16; o > 0; o >>= 1) {
        s  += __shfl_xor_sync(0xffffffffu, s,  o);
        s2 += __shfl_xor_sync(0xffffffffu, s2, o);
    }
    float mean = s * (1.f / 192.f);
    float var  = s2 * (1.f / 192.f) - mean * mean;
    float inv  = rsqrtf(var + 1e-5f);

    size_t drow;
    if (WINDOW_DST) {
        int bb  = tok >> 16;
        int rem = tok & 65535;
        int h   = rem >> 8;
        int w   = rem & 255;
        int win = (bb << 10) + ((h >> 3) << 5) + (w >> 3);
        int n   = ((h & 7) << 3) + (w & 7);
        drow = (size_t)win * 64 + n;
    } else {
        drow = (size_t)tok;
    }
    float* orow = out + drow * CDIM;
#pragma unroll
    for (int k = 0; k < 6; k++) {
        int c = lane + 32 * k;
        orow[c] = (v[k] - mean) * inv * g[c] + b[c];
    }
}

// ---------------- GEMM: tf32 wmma, 128x64 block, BK=32, double-buffered ----------------
#define BM 128
#define BN 64
#define BK 32

enum { EPI_QKV = 0, EPI_PROJ = 1, EPI_FC1 = 2, EPI_FC2 = 3 };

struct GemmSmem {
    union {
        struct { float a[2][BM][BK + 4]; float b[2][BK][BN + 4]; } ab;
        float c[BM][BN + 4];
    };
};
#define GEMM_SMEM_BYTES sizeof(GemmSmem)

__device__ __forceinline__ float4 tf32x4(float4 v) {
    v.x = wmma::__float_to_tf32(v.x);
    v.y = wmma::__float_to_tf32(v.y);
    v.z = wmma::__float_to_tf32(v.z);
    v.w = wmma::__float_to_tf32(v.w);
    return v;
}

template<int KDIM, int NDIM, int EPI>
__global__ __launch_bounds__(256, 2) void gemm_kernel(const float* __restrict__ A,
                                                      const float* __restrict__ B,
                                                      const float* __restrict__ bias,
                                                      const float* __restrict__ res,
                                                      float* __restrict__ out)
{
    extern __shared__ char smraw[];
    GemmSmem& sm = *reinterpret_cast<GemmSmem*>(smraw);

    const int bn   = blockIdx.x;
    const int bm   = blockIdx.y;
    const int tid  = threadIdx.x;
    const int warp = tid >> 5;
    const int wrow = warp >> 1;  // 0..3 : 32-row group
    const int wcol = warp & 1;   // 0..1 : 32-col group

    // global-load index precompute
    const int ar  = tid >> 3;          // 0..31  (A: rows tid>>3 + 32*s)
    const int ac4 = tid & 7;           // 0..7   A col group
    const int br  = tid >> 4;          // 0..15  (B: rows tid>>4 + 16*s)
    const int bc4 = tid & 15;          // 0..15  B col group

    const float* Abase = A + (size_t)(bm * BM) * KDIM;
    const float* Bbase = B + (size_t)bn * BN;

    wmma::fragment<wmma::accumulator, 16, 16, 8, float> acc[2][2];
#pragma unroll
    for (int i = 0; i < 2; i++)
#pragma unroll
        for (int j = 0; j < 2; j++) wmma::fill_fragment(acc[i][j], 0.f);

    float4 pa[4], pb[2];

    // prologue: load tile 0
#pragma unroll
    for (int s = 0; s < 4; s++)
        pa[s] = *(const float4*)(Abase + (size_t)(ar + 32 * s) * KDIM + ac4 * 4);
#pragma unroll
    for (int s = 0; s < 2; s++)
        pb[s] = *(const float4*)(Bbase + (size_t)(br + 16 * s) * NDIM + bc4 * 4);
#pragma unroll
    for (int s = 0; s < 4; s++) *(float4*)&sm.ab.a[0][ar + 32 * s][ac4 * 4] = tf32x4(pa[s]);
#pragma unroll
    for (int s = 0; s < 2; s++) *(float4*)&sm.ab.b[0][br + 16 * s][bc4 * 4] = tf32x4(pb[s]);
    __syncthreads();

    const int NK = KDIM / BK;
#pragma unroll 1
    for (int kt = 0; kt < NK; kt++) {
        const int cur = kt & 1;
        // prefetch next tile into registers
        if (kt + 1 < NK) {
            const int k0 = (kt + 1) * BK;
#pragma unroll
            for (int s = 0; s < 4; s++)
                pa[s] = *(const float4*)(Abase + (size_t)(ar + 32 * s) * KDIM + k0 + ac4 * 4);
#pragma unroll
            for (int s = 0; s < 2; s++)
                pb[s] = *(const float4*)(Bbase + (size_t)(k0 + br + 16 * s) * NDIM + bc4 * 4);
        }
        // compute on current buffer
#pragma unroll
        for (int kk = 0; kk < BK; kk += 8) {
            wmma::fragment<wmma::matrix_a, 16, 16, 8, wmma::precision::tf32, wmma::row_major> af[2];
            wmma::fragment<wmma::matrix_b, 16, 16, 8, wmma::precision::tf32, wmma::row_major> bf[2];
#pragma unroll
            for (int i = 0; i < 2; i++)
                wmma::load_matrix_sync(af[i], &sm.ab.a[cur][wrow * 32 + i * 16][kk], BK + 4);
#pragma unroll
            for (int j = 0; j < 2; j++)
                wmma::load_matrix_sync(bf[j], &sm.ab.b[cur][kk][wcol * 32 + j * 16], BN + 4);
#pragma unroll
            for (int i = 0; i < 2; i++)
#pragma unroll
                for (int j = 0; j < 2; j++)
                    wmma::mma_sync(acc[i][j], af[i], bf[j], acc[i][j]);
        }
        // store prefetched tile to the other buffer
        if (kt + 1 < NK) {
            const int nxt = (kt + 1) & 1;
#pragma unroll
            for (int s = 0; s < 4; s++) *(float4*)&sm.ab.a[nxt][ar + 32 * s][ac4 * 4] = tf32x4(pa[s]);
#pragma unroll
            for (int s = 0; s < 2; s++) *(float4*)&sm.ab.b[nxt][br + 16 * s][bc4 * 4] = tf32x4(pb[s]);
        }
        __syncthreads();
    }

    // accumulators -> smem C tile
#pragma unroll
    for (int i = 0; i < 2; i++)
#pragma unroll
        for (int j = 0; j < 2; j++)
            wmma::store_matrix_sync(&sm.c[wrow * 32 + i * 16][wcol * 32 + j * 16],
                                    acc[i][j], BN + 4, wmma::mem_row_major);
    __syncthreads();

    // epilogue: float4-vectorized
#pragma unroll
    for (int e = tid; e < BM * (BN / 4); e += 256) {
        int r  = e >> 4;
        int c4 = e & 15;
        int gcol = bn * BN + c4 * 4;
        size_t grow = (size_t)bm * BM + r;
        float4 v  = *(float4*)&sm.c[r][c4 * 4];
        float4 bb = *(const float4*)&bias[gcol];
        v.x += bb.x; v.y += bb.y; v.z += bb.z; v.w += bb.w;

        if constexpr (EPI == EPI_QKV) {
            *(float4*)&out[grow * NDIM + gcol] = v;
        } else if constexpr (EPI == EPI_PROJ) {
            int rg  = (int)grow;
            int win = rg >> 6, n = rg & 63;
            int bbi = win >> 10, wr = win & 1023;
            int h   = ((wr >> 5) << 3) + (n >> 3);
            int w   = ((wr & 31) << 3) + (n & 7);
            size_t t = ((size_t)bbi << 16) + ((size_t)h << 8) + (size_t)w;
            float4 rr = *(const float4*)&res[t * CDIM + gcol];
            v.x += rr.x; v.y += rr.y; v.z += rr.z; v.w += rr.w;
            *(float4*)&out[t * CDIM + gcol] = v;
        } else if constexpr (EPI == EPI_FC1) {
            v.x *= normcdff(v.x); v.y *= normcdff(v.y);
            v.z *= normcdff(v.z); v.w *= normcdff(v.w);
            *(float4*)&out[grow * NDIM + gcol] = v;
        } else {  // EPI_FC2
            float4 rr = *(const float4*)&res[grow * (size_t)CDIM + gcol];
            v.x += rr.x; v.y += rr.y; v.z += rr.z; v.w += rr.w;
            *(float4*)&out[grow * (size_t)NDIM + gcol] = v;
        }
    }
}

// ---------------- attention: one block per (window, head), fp32 ----------------
__global__ __launch_bounds__(128) void attn_kernel(const float* __restrict__ qkv,
                                                   float* __restrict__ o)
{
    __shared__ float qs[64][36];
    __shared__ float ks[64][32];
    __shared__ float vs[64][32];
    __shared__ float ps[64][68];

    const int head = blockIdx.x;     // 0..5
    const int win  = blockIdx.y;     // 0..4095
    const int tid  = threadIdx.x;

    const float* base = qkv + (size_t)win * 64 * 576 + head * 32;

#pragma unroll
    for (int t = 0; t < 4; t++) {
        int idx = tid + t * 128;
        int r = idx >> 3, c4 = idx & 7;
        const float* rp = base + (size_t)r * 576;
        *(float4*)&qs[r][c4 * 4] = *(const float4*)(rp +       c4 * 4);
        *(float4*)&ks[r][c4 * 4] = *(const float4*)(rp + 192 + c4 * 4);
        *(float4*)&vs[r][c4 * 4] = *(const float4*)(rp + 384 + c4 * 4);
    }
    __syncthreads();

    const int i    = tid >> 1;
    const int half = tid & 1;
    const int j0   = half * 32;

    float qr[32];
#pragma unroll
    for (int c4 = 0; c4 < 8; c4++)
        *(float4*)&qr[c4 * 4] = *(float4*)&qs[i][c4 * 4];

    float sv[32];
#pragma unroll
    for (int jj = 0; jj < 32; jj++) {
        int j = j0 + jj;
        float a = 0.f;
#pragma unroll
        for (int c4 = 0; c4 < 8; c4++) {
            float4 kv = *(float4*)&ks[j][c4 * 4];
            a += qr[c4 * 4 + 0] * kv.x;
            a += qr[c4 * 4 + 1] * kv.y;
            a += qr[c4 * 4 + 2] * kv.z;
            a += qr[c4 * 4 + 3] * kv.w;
        }
        sv[jj] = a * 0.17677669529663687f;
    }

    float m = -1e30f;
#pragma unroll
    for (int jj = 0; jj < 32; jj++) m = fmaxf(m, sv[jj]);
    m = fmaxf(m, __shfl_xor_sync(0xffffffffu, m, 1));
    float sum = 0.f;
#pragma unroll
    for (int jj = 0; jj < 32; jj++) { sv[jj] = __expf(sv[jj] - m); sum += sv[jj]; }
    sum += __shfl_xor_sync(0xffffffffu, sum, 1);
    float rinv = 1.f / sum;
#pragma unroll
    for (int c4 = 0; c4 < 8; c4++) {
        float4 p = make_float4(sv[c4 * 4] * rinv, sv[c4 * 4 + 1] * rinv,
                               sv[c4 * 4 + 2] * rinv, sv[c4 * 4 + 3] * rinv);
        *(float4*)&ps[i][j0 + c4 * 4] = p;
    }
    __syncwarp();

    float oacc[16];
#pragma unroll
    for (int t = 0; t < 16; t++) oacc[t] = 0.f;
#pragma unroll
    for (int j = 0; j < 64; j++) {
        float p = ps[i][j];
#pragma unroll
        for (int c4 = 0; c4 < 4; c4++) {
            float4 vv = *(float4*)&vs[j][half * 16 + c4 * 4];
            oacc[c4 * 4 + 0] += p * vv.x;
            oacc[c4 * 4 + 1] += p * vv.y;
            oacc[c4 * 4 + 2] += p * vv.z;
            oacc[c4 * 4 + 3] += p * vv.w;
        }
    }
    float* orow = o + (size_t)(win * 64 + i) * CDIM + head * 32 + half * 16;
#pragma unroll
    for (int c4 = 0; c4 < 4; c4++)
        *(float4*)&orow[c4 * 4] = make_float4(oacc[c4 * 4], oacc[c4 * 4 + 1],
                                              oacc[c4 * 4 + 2], oacc[c4 * 4 + 3]);
}

// ---------------- launch ----------------
extern "C" void kernel_launch(void* const* d_in, const int* in_sizes, int n_in,
                              void* d_out, int out_size)
{
    (void)in_sizes; (void)n_in; (void)out_size;
    const float* x      = (const float*)d_in[0];
    const float* g1     = (const float*)d_in[1];
    const float* b1     = (const float*)d_in[2];
    const float* w_qkv  = (const float*)d_in[3];
    const float* b_qkv  = (const float*)d_in[4];
    const float* w_proj = (const float*)d_in[5];
    const float* b_proj = (const float*)d_in[6];
    const float* g2     = (const float*)d_in[7];
    const float* b2     = (const float*)d_in[8];
    const float* w_fc1  = (const float*)d_in[9];
    const float* b_fc1  = (const float*)d_in[10];
    const float* w_fc2  = (const float*)d_in[11];
    const float* b_fc2  = (const float*)d_in[12];
    float* out = (float*)d_out;

    float *ln, *big, *ow, *xo;
    cudaGetSymbolAddress((void**)&ln,  g_ln);
    cudaGetSymbolAddress((void**)&big, g_big);
    cudaGetSymbolAddress((void**)&ow,  g_ow);
    cudaGetSymbolAddress((void**)&xo,  g_xo);

    const int SB = (int)GEMM_SMEM_BYTES;
    cudaFuncSetAttribute(gemm_kernel<192, 576, EPI_QKV>,  cudaFuncAttributeMaxDynamicSharedMemorySize, SB);
    cudaFuncSetAttribute(gemm_kernel<192, 192, EPI_PROJ>, cudaFuncAttributeMaxDynamicSharedMemorySize, SB);
    cudaFuncSetAttribute(gemm_kernel<192, 768, EPI_FC1>,  cudaFuncAttributeMaxDynamicSharedMemorySize, SB);
    cudaFuncSetAttribute(gemm_kernel<768, 192, EPI_FC2>,  cudaFuncAttributeMaxDynamicSharedMemorySize, SB);

    // 1. LN1 + window partition
    ln_kernel<true><<<TOK / 8, 256>>>(x, g1, b1, ln);
    // 2. QKV GEMM (window-ordered rows)
    gemm_kernel<192, 576, EPI_QKV><<<dim3(9, TOK / BM), 256, SB>>>(ln, w_qkv, b_qkv, nullptr, big);
    // 3. attention per (window, head)
    attn_kernel<<<dim3(6, 4096), 128>>>(big, ow);
    // 4. proj GEMM + window unpartition + residual x -> xo (token order)
    gemm_kernel<192, 192, EPI_PROJ><<<dim3(3, TOK / BM), 256, SB>>>(ow, w_proj, b_proj, x, xo);
    // 5. LN2 (token order)
    ln_kernel<false><<<TOK / 8, 256>>>(xo, g2, b2, ln);
    // 6. FC1 GEMM + exact GELU
    gemm_kernel<192, 768, EPI_FC1><<<dim3(12, TOK / BM), 256, SB>>>(ln, w_fc1, b_fc1, nullptr, big);
    // 7. FC2 GEMM + residual xo -> out
    gemm_kernel<768, 192, EPI_FC2><<<dim3(3, TOK / BM), 256, SB>>>(big, w_fc2, b_fc2, xo, out);
}

// round 3
// speedup vs baseline: 1.4892x; 1.0553x over previous
#include <cuda_runtime.h>
#include <mma.h>
#include <cstdint>

using namespace nvcuda;

#define TOK    262144          // 4*256*256 tokens
#define CDIM   192

// ---------------- scratch (device globals; no allocation) ----------------
__device__ float g_ln  [(size_t)TOK * 192];   // LN1 (window layout) then LN2 (token layout)
__device__ float g_big [(size_t)TOK * 768];   // qkv (576 wide) then fc1 activation (768 wide)
__device__ float g_ow  [(size_t)TOK * 192];   // attention output, window layout
__device__ float g_xo  [(size_t)TOK * 192];   // post-attention residual, token layout

// ---------------- cp.async helpers ----------------
__device__ __forceinline__ void cp_async16(void* smem_dst, const void* gmem_src) {
    uint32_t s = (uint32_t)__cvta_generic_to_shared(smem_dst);
    asm volatile("cp.async.cg.shared.global [%0], [%1], 16;\n" :: "r"(s), "l"(gmem_src));
}
__device__ __forceinline__ void cp_commit() {
    asm volatile("cp.async.commit_group;\n" ::: "memory");
}
template<int N>
__device__ __forceinline__ void cp_wait() {
    asm volatile("cp.async.wait_group %0;\n" :: "n"(N) : "memory");
}

// ---------------- LayerNorm (one warp per token) ----------------
template<bool WINDOW_DST>
__global__ __launch_bounds__(256) void ln_kernel(const float* __restrict__ x,
                                                 const float* __restrict__ g,
                                                 const float* __restrict__ b,
                                                 float* __restrict__ out)
{
    int tok  = blockIdx.x * (blockDim.x >> 5) + (threadIdx.x >> 5);
    int lane = threadIdx.x & 31;
    const float* row = x + (size_t)tok * CDIM;
    float v[6];
    float s = 0.f, s2 = 0.f;
#pragma unroll
    for (int k = 0; k < 6; k++) {
        v[k] = row[lane + 32 * k];
        s  += v[k];
        s2 += v[k] * v[k];
    }
#pragma unroll
    for (int o = 16; o > 0; o >>= 1) {
        s  += __shfl_xor_sync(0xffffffffu, s,  o);
        s2 += __shfl_xor_sync(0xffffffffu, s2, o);
    }
    float mean = s * (1.f / 192.f);
    float var  = s2 * (1.f / 192.f) - mean * mean;
    float inv  = rsqrtf(var + 1e-5f);

    size_t drow;
    if (WINDOW_DST) {
        int bb  = tok >> 16;
        int rem = tok & 65535;
        int h   = rem >> 8;
        int w   = rem & 255;
        int win = (bb << 10) + ((h >> 3) << 5) + (w >> 3);
        int n   = ((h & 7) << 3) + (w & 7);
        drow = (size_t)win * 64 + n;
    } else {
        drow = (size_t)tok;
    }
    float* orow = out + drow * CDIM;
#pragma unroll
    for (int k = 0; k < 6; k++) {
        int c = lane + 32 * k;
        orow[c] = (v[k] - mean) * inv * g[c] + b[c];
    }
}

// ---------------- GEMM: tf32 wmma, 64x192 block, BK=32, cp.async 2-stage ----------------
#define BM 64
#define BN 192
#define BK 32

#define APAD 4
#define BPAD 4
#define ALD  (BK + APAD)      // 36
#define BLD  (BN + BPAD)      // 196
#define SA_ELE (BM * ALD)     // 2304
#define SB_ELE (BK * BLD)     // 6272
#define GEMM_SMEM_BYTES ((2 * SA_ELE + 2 * SB_ELE) * 4)   // 68608 B

enum { EPI_QKV = 0, EPI_PROJ = 1, EPI_FC1 = 2, EPI_FC2 = 3 };

template<int KDIM, int NDIM, int EPI>
__global__ __launch_bounds__(256, 2) void gemm_kernel(const float* __restrict__ A,
                                                      const float* __restrict__ B,
                                                      const float* __restrict__ bias,
                                                      const float* __restrict__ res,
                                                      float* __restrict__ out)
{
    extern __shared__ float sm[];
    float* sa[2] = { sm, sm + SA_ELE };
    float* sb[2] = { sm + 2 * SA_ELE, sm + 2 * SA_ELE + SB_ELE };
    float* csm   = sm;   // epilogue reuse (64*196 = 12544 floats < 17152)

    const int bn   = blockIdx.x;
    const int bm   = blockIdx.y;
    const int tid  = threadIdx.x;
    const int warp = tid >> 5;
    const int wr   = warp >> 2;   // 0..1 : 32-row group
    const int wc   = warp & 3;    // 0..3 : 48-col group

    // A loads: 512 lines (16B); thread handles lines tid, tid+256
    const int a_r0  = tid >> 3;      // 0..31
    const int a_c4  = tid & 7;       // 0..7
    // B loads: 1536 lines; 6 per thread: line = tid + s*256
    const float* Abase = A + (size_t)(bm * BM) * KDIM;
    const float* Bbase = B + (size_t)bn * BN;

    wmma::fragment<wmma::accumulator, 16, 16, 8, float> acc[2][3];
#pragma unroll
    for (int i = 0; i < 2; i++)
#pragma unroll
        for (int j = 0; j < 3; j++) wmma::fill_fragment(acc[i][j], 0.f);

    auto issue_stage = [&](int buf, int k0) {
        // A tile 64x32
#pragma unroll
        for (int s = 0; s < 2; s++) {
            int r = a_r0 + 32 * s;
            cp_async16(&sa[buf][r * ALD + a_c4 * 4],
                       Abase + (size_t)r * KDIM + k0 + a_c4 * 4);
        }
        // B tile 32x192
#pragma unroll
        for (int s = 0; s < 6; s++) {
            int line = tid + s * 256;
            int r  = line / 48;
            int c4 = line % 48;
            cp_async16(&sb[buf][r * BLD + c4 * 4],
                       Bbase + (size_t)(k0 + r) * NDIM + c4 * 4);
        }
        cp_commit();
    };

    issue_stage(0, 0);

    const int NK = KDIM / BK;
#pragma unroll 1
    for (int kt = 0; kt < NK; kt++) {
        const int cur = kt & 1;
        if (kt + 1 < NK) {
            issue_stage((kt + 1) & 1, (kt + 1) * BK);
            cp_wait<1>();
        } else {
            cp_wait<0>();
        }
        __syncthreads();

#pragma unroll
        for (int kk = 0; kk < BK; kk += 8) {
            wmma::fragment<wmma::matrix_a, 16, 16, 8, wmma::precision::tf32, wmma::row_major> af[2];
            wmma::fragment<wmma::matrix_b, 16, 16, 8, wmma::precision::tf32, wmma::row_major> bf[3];
#pragma unroll
            for (int i = 0; i < 2; i++)
                wmma::load_matrix_sync(af[i], &sa[cur][(wr * 32 + i * 16) * ALD + kk], ALD);
#pragma unroll
            for (int j = 0; j < 3; j++)
                wmma::load_matrix_sync(bf[j], &sb[cur][kk * BLD + wc * 48 + j * 16], BLD);
#pragma unroll
            for (int i = 0; i < 2; i++)
#pragma unroll
                for (int j = 0; j < 3; j++)
                    wmma::mma_sync(acc[i][j], af[i], bf[j], acc[i][j]);
        }
        __syncthreads();
    }

    // accumulators -> smem C tile (reuses pipeline smem; all compute done)
#pragma unroll
    for (int i = 0; i < 2; i++)
#pragma unroll
        for (int j = 0; j < 3; j++)
            wmma::store_matrix_sync(&csm[(wr * 32 + i * 16) * BLD + wc * 48 + j * 16],
                                    acc[i][j], BLD, wmma::mem_row_major);
    __syncthreads();

    // epilogue: 64x192 = 3072 float4, 12 per thread
#pragma unroll
    for (int e = tid; e < BM * (BN / 4); e += 256) {
        int r  = e / 48;
        int c4 = e % 48;
        int gcol = bn * BN + c4 * 4;
        size_t grow = (size_t)bm * BM + r;
        float4 v  = *(float4*)&csm[r * BLD + c4 * 4];
        float4 bb = *(const float4*)&bias[gcol];
        v.x += bb.x; v.y += bb.y; v.z += bb.z; v.w += bb.w;

        if constexpr (EPI == EPI_QKV) {
            *(float4*)&out[grow * NDIM + gcol] = v;
        } else if constexpr (EPI == EPI_PROJ) {
            int rg  = (int)grow;
            int win = rg >> 6, n = rg & 63;
            int bbi = win >> 10, wrw = win & 1023;
            int h   = ((wrw >> 5) << 3) + (n >> 3);
            int w   = ((wrw & 31) << 3) + (n & 7);
            size_t t = ((size_t)bbi << 16) + ((size_t)h << 8) + (size_t)w;
            float4 rr = *(const float4*)&res[t * CDIM + gcol];
            v.x += rr.x; v.y += rr.y; v.z += rr.z; v.w += rr.w;
            *(float4*)&out[t * CDIM + gcol] = v;
        } else if constexpr (EPI == EPI_FC1) {
            v.x *= normcdff(v.x); v.y *= normcdff(v.y);
            v.z *= normcdff(v.z); v.w *= normcdff(v.w);
            *(float4*)&out[grow * NDIM + gcol] = v;
        } else {  // EPI_FC2
            float4 rr = *(const float4*)&res[grow * (size_t)CDIM + gcol];
            v.x += rr.x; v.y += rr.y; v.z += rr.z; v.w += rr.w;
            *(float4*)&out[grow * (size_t)NDIM + gcol] = v;
        }
    }
}

// ---------------- attention: one block per (window, head), fp32 ----------------
__global__ __launch_bounds__(128) void attn_kernel(const float* __restrict__ qkv,
                                                   float* __restrict__ o)
{
    __shared__ float qs[64][36];
    __shared__ float ks[64][32];
    __shared__ float vs[64][32];
    __shared__ float ps[64][68];

    const int head = blockIdx.x;     // 0..5
    const int win  = blockIdx.y;     // 0..4095
    const int tid  = threadIdx.x;

    const float* base = qkv + (size_t)win * 64 * 576 + head * 32;

#pragma unroll
    for (int t = 0; t < 4; t++) {
        int idx = tid + t * 128;
        int r = idx >> 3, c4 = idx & 7;
        const float* rp = base + (size_t)r * 576;
        *(float4*)&qs[r][c4 * 4] = *(const float4*)(rp +       c4 * 4);
        *(float4*)&ks[r][c4 * 4] = *(const float4*)(rp + 192 + c4 * 4);
        *(float4*)&vs[r][c4 * 4] = *(const float4*)(rp + 384 + c4 * 4);
    }
    __syncthreads();

    const int i    = tid >> 1;
    const int half = tid & 1;
    const int j0   = half * 32;

    float qr[32];
#pragma unroll
    for (int c4 = 0; c4 < 8; c4++)
        *(float4*)&qr[c4 * 4] = *(float4*)&qs[i][c4 * 4];

    float sv[32];
#pragma unroll
    for (int jj = 0; jj < 32; jj++) {
        int j = j0 + jj;
        float a = 0.f;
#pragma unroll
        for (int c4 = 0; c4 < 8; c4++) {
            float4 kv = *(float4*)&ks[j][c4 * 4];
            a += qr[c4 * 4 + 0] * kv.x;
            a += qr[c4 * 4 + 1] * kv.y;
            a += qr[c4 * 4 + 2] * kv.z;
            a += qr[c4 * 4 + 3] * kv.w;
        }
        sv[jj] = a * 0.17677669529663687f;
    }

    float m = -1e30f;
#pragma unroll
    for (int jj = 0; jj < 32; jj++) m = fmaxf(m, sv[jj]);
    m = fmaxf(m, __shfl_xor_sync(0xffffffffu, m, 1));
    float sum = 0.f;
#pragma unroll
    for (int jj = 0; jj < 32; jj++) { sv[jj] = __expf(sv[jj] - m); sum += sv[jj]; }
    sum += __shfl_xor_sync(0xffffffffu, sum, 1);
    float rinv = 1.f / sum;
#pragma unroll
    for (int c4 = 0; c4 < 8; c4++) {
        float4 p = make_float4(sv[c4 * 4] * rinv, sv[c4 * 4 + 1] * rinv,
                               sv[c4 * 4 + 2] * rinv, sv[c4 * 4 + 3] * rinv);
        *(float4*)&ps[i][j0 + c4 * 4] = p;
    }
    __syncwarp();

    float oacc[16];
#pragma unroll
    for (int t = 0; t < 16; t++) oacc[t] = 0.f;
#pragma unroll
    for (int j = 0; j < 64; j++) {
        float p = ps[i][j];
#pragma unroll
        for (int c4 = 0; c4 < 4; c4++) {
            float4 vv = *(float4*)&vs[j][half * 16 + c4 * 4];
            oacc[c4 * 4 + 0] += p * vv.x;
            oacc[c4 * 4 + 1] += p * vv.y;
            oacc[c4 * 4 + 2] += p * vv.z;
            oacc[c4 * 4 + 3] += p * vv.w;
        }
    }
    float* orow = o + (size_t)(win * 64 + i) * CDIM + head * 32 + half * 16;
#pragma unroll
    for (int c4 = 0; c4 < 4; c4++)
        *(float4*)&orow[c4 * 4] = make_float4(oacc[c4 * 4], oacc[c4 * 4 + 1],
                                              oacc[c4 * 4 + 2], oacc[c4 * 4 + 3]);
}

// ---------------- launch ----------------
extern "C" void kernel_launch(void* const* d_in, const int* in_sizes, int n_in,
                              void* d_out, int out_size)
{
    (void)in_sizes; (void)n_in; (void)out_size;
    const float* x      = (const float*)d_in[0];
    const float* g1     = (const float*)d_in[1];
    const float* b1     = (const float*)d_in[2];
    const float* w_qkv  = (const float*)d_in[3];
    const float* b_qkv  = (const float*)d_in[4];
    const float* w_proj = (const float*)d_in[5];
    const float* b_proj = (const float*)d_in[6];
    const float* g2     = (const float*)d_in[7];
    const float* b2     = (const float*)d_in[8];
    const float* w_fc1  = (const float*)d_in[9];
    const float* b_fc1  = (const float*)d_in[10];
    const float* w_fc2  = (const float*)d_in[11];
    const float* b_fc2  = (const float*)d_in[12];
    float* out = (float*)d_out;

    float *ln, *big, *ow, *xo;
    cudaGetSymbolAddress((void**)&ln,  g_ln);
    cudaGetSymbolAddress((void**)&big, g_big);
    cudaGetSymbolAddress((void**)&ow,  g_ow);
    cudaGetSymbolAddress((void**)&xo,  g_xo);

    const int SB = (int)GEMM_SMEM_BYTES;
    cudaFuncSetAttribute(gemm_kernel<192, 576, EPI_QKV>,  cudaFuncAttributeMaxDynamicSharedMemorySize, SB);
    cudaFuncSetAttribute(gemm_kernel<192, 192, EPI_PROJ>, cudaFuncAttributeMaxDynamicSharedMemorySize, SB);
    cudaFuncSetAttribute(gemm_kernel<192, 768, EPI_FC1>,  cudaFuncAttributeMaxDynamicSharedMemorySize, SB);
    cudaFuncSetAttribute(gemm_kernel<768, 192, EPI_FC2>,  cudaFuncAttributeMaxDynamicSharedMemorySize, SB);

    // 1. LN1 + window partition
    ln_kernel<true><<<TOK / 8, 256>>>(x, g1, b1, ln);
    // 2. QKV GEMM (window-ordered rows): 3 column passes of 192
    gemm_kernel<192, 576, EPI_QKV><<<dim3(3, TOK / BM), 256, SB>>>(ln, w_qkv, b_qkv, nullptr, big);
    // 3. attention per (window, head)
    attn_kernel<<<dim3(6, 4096), 128>>>(big, ow);
    // 4. proj GEMM + window unpartition + residual x -> xo (token order)
    gemm_kernel<192, 192, EPI_PROJ><<<dim3(1, TOK / BM), 256, SB>>>(ow, w_proj, b_proj, x, xo);
    // 5. LN2 (token order)
    ln_kernel<false><<<TOK / 8, 256>>>(xo, g2, b2, ln);
    // 6. FC1 GEMM + exact GELU: 4 column passes
    gemm_kernel<192, 768, EPI_FC1><<<dim3(4, TOK / BM), 256, SB>>>(ln, w_fc1, b_fc1, nullptr, big);
    // 7. FC2 GEMM + residual xo -> out
    gemm_kernel<768, 192, EPI_FC2><<<dim3(1, TOK / BM), 256, SB>>>(big, w_fc2, b_fc2, xo, out);
}

// round 5
// speedup vs baseline: 2.7272x; 1.8313x over previous
#include <cuda_runtime.h>
#include <cuda_fp16.h>
#include <mma.h>
#include <cstdint>

using namespace nvcuda;

#define TOK    262144          // 4*256*256 tokens
#define CDIM   192

// ---------------- scratch (device globals; no allocation) ----------------
__device__ __half g_ln  [(size_t)TOK * 192];   // LN1 (window layout) then LN2 (token layout)
__device__ __half g_big [(size_t)TOK * 768];   // qkv (576 wide) then fc1 activation (768 wide)
__device__ __half g_ow  [(size_t)TOK * 192];   // attention output, window layout
__device__ float  g_xo  [(size_t)TOK * 192];   // post-attention residual, token layout (fp32)
__device__ __half g_wqkv_h[192 * 576];
__device__ __half g_wproj_h[192 * 192];
__device__ __half g_wfc1_h[192 * 768];
__device__ __half g_wfc2_h[768 * 192];

// ---------------- cp.async helpers ----------------
__device__ __forceinline__ void cp_async16(void* smem_dst, const void* gmem_src) {
    uint32_t s = (uint32_t)__cvta_generic_to_shared(smem_dst);
    asm volatile("cp.async.cg.shared.global [%0], [%1], 16;\n" :: "r"(s), "l"(gmem_src));
}
__device__ __forceinline__ void cp_commit() {
    asm volatile("cp.async.commit_group;\n" ::: "memory");
}
template<int N>
__device__ __forceinline__ void cp_wait() {
    asm volatile("cp.async.wait_group %0;\n" :: "n"(N) : "memory");
}

// ---------------- fp32 -> fp16 weight conversion ----------------
__global__ __launch_bounds__(256) void f2h_kernel(const float* __restrict__ in,
                                                  __half* __restrict__ out, int n4)
{
    int i = blockIdx.x * 256 + threadIdx.x;
    if (i < n4) {
        float4 v = *(const float4*)(in + (size_t)i * 4);
        __half2 h0 = __floats2half2_rn(v.x, v.y);
        __half2 h1 = __floats2half2_rn(v.z, v.w);
        *(uint2*)(out + (size_t)i * 4) = make_uint2(*(uint32_t*)&h0, *(uint32_t*)&h1);
    }
}

// ---------------- LayerNorm (one warp per token), fp16 output ----------------
template<bool WINDOW_DST>
__global__ __launch_bounds__(256) void ln_kernel(const float* __restrict__ x,
                                                 const float* __restrict__ g,
                                                 const float* __restrict__ b,
                                                 __half* __restrict__ out)
{
    int tok  = blockIdx.x * (blockDim.x >> 5) + (threadIdx.x >> 5);
    int lane = threadIdx.x & 31;
    const float* row = x + (size_t)tok * CDIM;
    float v[6];
    float s = 0.f, s2 = 0.f;
#pragma unroll
    for (int k = 0; k < 6; k++) {
        v[k] = row[lane + 32 * k];
        s  += v[k];
        s2 += v[k] * v[k];
    }
#pragma unroll
    for (int o = 16; o > 0; o >>= 1) {
        s  += __shfl_xor_sync(0xffffffffu, s,  o);
        s2 += __shfl_xor_sync(0xffffffffu, s2, o);
    }
    float mean = s * (1.f / 192.f);
    float var  = s2 * (1.f / 192.f) - mean * mean;
    float inv  = rsqrtf(var + 1e-5f);

    size_t drow;
    if (WINDOW_DST) {
        int bb  = tok >> 16;
        int rem = tok & 65535;
        int h   = rem >> 8;
        int w   = rem & 255;
        int win = (bb << 10) + ((h >> 3) << 5) + (w >> 3);
        int n   = ((h & 7) << 3) + (w & 7);
        drow = (size_t)win * 64 + n;
    } else {
        drow = (size_t)tok;
    }
    __half* orow = out + drow * CDIM;
#pragma unroll
    for (int k = 0; k < 6; k++) {
        int c = lane + 32 * k;
        orow[c] = __float2half_rn((v[k] - mean) * inv * g[c] + b[c]);
    }
}

// ---------------- GEMM: fp16 wmma m16n16k16, 64x192 block, BK=64, cp.async 2-stage ----------------
#define GBM 64
#define GBN 192
#define GBK 64

#define ALDH 80     // 64 + 16 halves pad  (row = 160 B)
#define BLDH 208    // 192 + 16 halves pad (row = 416 B)
#define SA_HALF (GBM * ALDH)    // 5120 halves
#define SB_HALF (GBK * BLDH)    // 13312 halves
#define PIPE_BYTES ((2 * SA_HALF + 2 * SB_HALF) * 2)   // 73728 B
#define CLD 196
#define GEMM_DYN PIPE_BYTES     // epilogue fp32 tile 64*196*4 = 50176 < 73728

enum { EPI_QKV = 0, EPI_PROJ = 1, EPI_FC1 = 2, EPI_FC2 = 3 };

// A: [M][KDIM] half row-major; B: [KDIM][NDIM] half row-major.
template<int KDIM, int NDIM, int EPI>
__global__ __launch_bounds__(256, 2) void gemm_kernel(const __half* __restrict__ A,
                                                      const __half* __restrict__ B,
                                                      const float* __restrict__ bias,
                                                      const float* __restrict__ res,
                                                      void* __restrict__ out_v)
{
    extern __shared__ char dynsm[];
    __half* sa[2] = { (__half*)dynsm, (__half*)dynsm + SA_HALF };
    __half* sb[2] = { (__half*)dynsm + 2 * SA_HALF, (__half*)dynsm + 2 * SA_HALF + SB_HALF };
    float*  csm   = (float*)dynsm;

    const int bn   = blockIdx.x;
    const int bm   = blockIdx.y;
    const int tid  = threadIdx.x;
    const int warp = tid >> 5;
    const int wr   = warp >> 2;   // 0..1 : 32-row group
    const int wc   = warp & 3;    // 0..3 : 48-col group

    const __half* Abase = A + (size_t)(bm * GBM) * KDIM;
    const __half* Bbase = B + (size_t)bn * GBN;

    wmma::fragment<wmma::accumulator, 16, 16, 16, float> acc[2][3];
#pragma unroll
    for (int i = 0; i < 2; i++)
#pragma unroll
        for (int j = 0; j < 3; j++) wmma::fill_fragment(acc[i][j], 0.f);

    auto issue_stage = [&](int buf, int k0) {
        // A tile 64x64 halves: 512 x 16B lines, 2/thread
#pragma unroll
        for (int s = 0; s < 2; s++) {
            int line = tid + s * 256;
            int r = line >> 3, c8 = line & 7;
            cp_async16(&sa[buf][r * ALDH + c8 * 8],
                       Abase + (size_t)r * KDIM + k0 + c8 * 8);
        }
        // B tile 64x192 halves: 1536 x 16B lines, 6/thread
#pragma unroll
        for (int s = 0; s < 6; s++) {
            int line = tid + s * 256;
            int r = line / 24, c8 = line % 24;
            cp_async16(&sb[buf][r * BLDH + c8 * 8],
                       Bbase + (size_t)(k0 + r) * NDIM + c8 * 8);
        }
        cp_commit();
    };

    issue_stage(0, 0);

    constexpr int NK = KDIM / GBK;
#pragma unroll 1
    for (int kt = 0; kt < NK; kt++) {
        const int cur = kt & 1;
        if (kt + 1 < NK) {
            issue_stage((kt + 1) & 1, (kt + 1) * GBK);
            cp_wait<1>();
        } else {
            cp_wait<0>();
        }
        __syncthreads();

#pragma unroll
        for (int kk = 0; kk < GBK; kk += 16) {
            wmma::fragment<wmma::matrix_a, 16, 16, 16, __half, wmma::row_major> af[2];
            wmma::fragment<wmma::matrix_b, 16, 16, 16, __half, wmma::row_major> bf[3];
#pragma unroll
            for (int i = 0; i < 2; i++)
                wmma::load_matrix_sync(af[i], &sa[cur][(wr * 32 + i * 16) * ALDH + kk], ALDH);
#pragma unroll
            for (int j = 0; j < 3; j++)
                wmma::load_matrix_sync(bf[j], &sb[cur][kk * BLDH + wc * 48 + j * 16], BLDH);
#pragma unroll
            for (int i = 0; i < 2; i++)
#pragma unroll
                for (int j = 0; j < 3; j++)
                    wmma::mma_sync(acc[i][j], af[i], bf[j], acc[i][j]);
        }
        __syncthreads();
    }

    // accumulators -> smem C tile (fp32), reusing pipeline smem
#pragma unroll
    for (int i = 0; i < 2; i++)
#pragma unroll
        for (int j = 0; j < 3; j++)
            wmma::store_matrix_sync(&csm[(wr * 32 + i * 16) * CLD + wc * 48 + j * 16],
                                    acc[i][j], CLD, wmma::mem_row_major);
    __syncthreads();

    // epilogue: 64x192 = 3072 float4-groups, 12 per thread
#pragma unroll
    for (int e = tid; e < GBM * (GBN / 4); e += 256) {
        int r  = e / 48;
        int c4 = e % 48;
        int gcol = bn * GBN + c4 * 4;
        size_t grow = (size_t)bm * GBM + r;
        float4 v  = *(float4*)&csm[r * CLD + c4 * 4];
        float4 bb = *(const float4*)&bias[gcol];
        v.x += bb.x; v.y += bb.y; v.z += bb.z; v.w += bb.w;

        if constexpr (EPI == EPI_QKV) {
            __half* out = (__half*)out_v;
            __half2 h0 = __floats2half2_rn(v.x, v.y);
            __half2 h1 = __floats2half2_rn(v.z, v.w);
            *(uint2*)&out[grow * NDIM + gcol] = make_uint2(*(uint32_t*)&h0, *(uint32_t*)&h1);
        } else if constexpr (EPI == EPI_PROJ) {
            float* out = (float*)out_v;
            int rg  = (int)grow;
            int win = rg >> 6, n = rg & 63;
            int bbi = win >> 10, wrw = win & 1023;
            int h   = ((wrw >> 5) << 3) + (n >> 3);
            int w   = ((wrw & 31) << 3) + (n & 7);
            size_t t = ((size_t)bbi << 16) + ((size_t)h << 8) + (size_t)w;
            float4 rr = *(const float4*)&res[t * CDIM + gcol];
            v.x += rr.x; v.y += rr.y; v.z += rr.z; v.w += rr.w;
            *(float4*)&out[t * CDIM + gcol] = v;
        } else if constexpr (EPI == EPI_FC1) {
            __half* out = (__half*)out_v;
            v.x *= normcdff(v.x); v.y *= normcdff(v.y);
            v.z *= normcdff(v.z); v.w *= normcdff(v.w);
            __half2 h0 = __floats2half2_rn(v.x, v.y);
            __half2 h1 = __floats2half2_rn(v.z, v.w);
            *(uint2*)&out[grow * NDIM + gcol] = make_uint2(*(uint32_t*)&h0, *(uint32_t*)&h1);
        } else {  // EPI_FC2
            float* out = (float*)out_v;
            float4 rr = *(const float4*)&res[grow * (size_t)CDIM + gcol];
            v.x += rr.x; v.y += rr.y; v.z += rr.z; v.w += rr.w;
            *(float4*)&out[grow * (size_t)NDIM + gcol] = v;
        }
    }
}

// ---------------- attention: one block per (window, head), fp32 math, fp16 I/O ----------------
__global__ __launch_bounds__(128) void attn_kernel(const __half* __restrict__ qkv,
                                                   __half* __restrict__ o)
{
    __shared__ float qs[64][36];
    __shared__ float ks[64][32];
    __shared__ float vs[64][32];
    __shared__ float ps[64][68];

    const int head = blockIdx.x;     // 0..5
    const int win  = blockIdx.y;     // 0..4095
    const int tid  = threadIdx.x;

    const __half* base = qkv + (size_t)win * 64 * 576 + head * 32;

    // load q,k,v tiles: 64x32 halves each; 256 x 16B lines per tensor, 2/thread
#pragma unroll
    for (int t = 0; t < 2; t++) {
        int idx = tid + t * 128;           // 0..255
        int r = idx >> 2, c8 = idx & 3;    // 4 lines of 8 halves per row
        const __half* rp = base + (size_t)r * 576;
#pragma unroll
        for (int which = 0; which < 3; which++) {
            const __half* src = rp + which * 192 + c8 * 8;
            uint2 raw = *(const uint2*)src;
            __half2 h0 = *(__half2*)&raw.x;
            __half2 h1 = *(__half2*)&raw.y;
            src += 4;
            uint2 raw2 = *(const uint2*)src;
            __half2 h2 = *(__half2*)&raw2.x;
            __half2 h3 = *(__half2*)&raw2.y;
            float* dst = (which == 0) ? &qs[r][c8 * 8] : (which == 1) ? &ks[r][c8 * 8] : &vs[r][c8 * 8];
            float2 f0 = __half22float2(h0), f1 = __half22float2(h1);
            float2 f2 = __half22float2(h2), f3 = __half22float2(h3);
            dst[0] = f0.x; dst[1] = f0.y; dst[2] = f1.x; dst[3] = f1.y;
            dst[4] = f2.x; dst[5] = f2.y; dst[6] = f3.x; dst[7] = f3.y;
        }
    }
    __syncthreads();

    const int i    = tid >> 1;
    const int half = tid & 1;
    const int j0   = half * 32;

    float qr[32];
#pragma unroll
    for (int c4 = 0; c4 < 8; c4++)
        *(float4*)&qr[c4 * 4] = *(float4*)&qs[i][c4 * 4];

    float sv[32];
#pragma unroll
    for (int jj = 0; jj < 32; jj++) {
        int j = j0 + jj;
        float a = 0.f;
#pragma unroll
        for (int c4 = 0; c4 < 8; c4++) {
            float4 kv = *(float4*)&ks[j][c4 * 4];
            a += qr[c4 * 4 + 0] * kv.x;
            a += qr[c4 * 4 + 1] * kv.y;
            a += qr[c4 * 4 + 2] * kv.z;
            a += qr[c4 * 4 + 3] * kv.w;
        }
        sv[jj] = a * 0.17677669529663687f;
    }

    float m = -1e30f;
#pragma unroll
    for (int jj = 0; jj < 32; jj++) m = fmaxf(m, sv[jj]);
    m = fmaxf(m, __shfl_xor_sync(0xffffffffu, m, 1));
    float sum = 0.f;
#pragma unroll
    for (int jj = 0; jj < 32; jj++) { sv[jj] = __expf(sv[jj] - m); sum += sv[jj]; }
    sum += __shfl_xor_sync(0xffffffffu, sum, 1);
    float rinv = 1.f / sum;
#pragma unroll
    for (int c4 = 0; c4 < 8; c4++) {
        float4 p = make_float4(sv[c4 * 4] * rinv, sv[c4 * 4 + 1] * rinv,
                               sv[c4 * 4 + 2] * rinv, sv[c4 * 4 + 3] * rinv);
        *(float4*)&ps[i][j0 + c4 * 4] = p;
    }
    __syncwarp();

    float oacc[16];
#pragma unroll
    for (int t = 0; t < 16; t++) oacc[t] = 0.f;
#pragma unroll
    for (int j = 0; j < 64; j++) {
        float p = ps[i][j];
#pragma unroll
        for (int c4 = 0; c4 < 4; c4++) {
            float4 vv = *(float4*)&vs[j][half * 16 + c4 * 4];
            oacc[c4 * 4 + 0] += p * vv.x;
            oacc[c4 * 4 + 1] += p * vv.y;
            oacc[c4 * 4 + 2] += p * vv.z;
            oacc[c4 * 4 + 3] += p * vv.w;
        }
    }
    __half* orow = o + (size_t)(win * 64 + i) * CDIM + head * 32 + half * 16;
#pragma unroll
    for (int c4 = 0; c4 < 4; c4++) {
        __half2 h0 = __floats2half2_rn(oacc[c4 * 4 + 0], oacc[c4 * 4 + 1]);
        __half2 h1 = __floats2half2_rn(oacc[c4 * 4 + 2], oacc[c4 * 4 + 3]);
        *(uint2*)&orow[c4 * 4] = make_uint2(*(uint32_t*)&h0, *(uint32_t*)&h1);
    }
}

// ---------------- launch ----------------
extern "C" void kernel_launch(void* const* d_in, const int* in_sizes, int n_in,
                              void* d_out, int out_size)
{
    (void)in_sizes; (void)n_in; (void)out_size;
    const float* x      = (const float*)d_in[0];
    const float* g1     = (const float*)d_in[1];
    const float* b1     = (const float*)d_in[2];
    const float* w_qkv  = (const float*)d_in[3];
    const float* b_qkv  = (const float*)d_in[4];
    const float* w_proj = (const float*)d_in[5];
    const float* b_proj = (const float*)d_in[6];
    const float* g2     = (const float*)d_in[7];
    const float* b2     = (const float*)d_in[8];
    const float* w_fc1  = (const float*)d_in[9];
    const float* b_fc1  = (const float*)d_in[10];
    const float* w_fc2  = (const float*)d_in[11];
    const float* b_fc2  = (const float*)d_in[12];
    float* out = (float*)d_out;

    __half *ln, *big, *ow, *wqkv_h, *wproj_h, *wfc1_h, *wfc2_h;
    float *xo;
    cudaGetSymbolAddress((void**)&ln,  g_ln);
    cudaGetSymbolAddress((void**)&big, g_big);
    cudaGetSymbolAddress((void**)&ow,  g_ow);
    cudaGetSymbolAddress((void**)&xo,  g_xo);
    cudaGetSymbolAddress((void**)&wqkv_h, g_wqkv_h);
    cudaGetSymbolAddress((void**)&wproj_h, g_wproj_h);
    cudaGetSymbolAddress((void**)&wfc1_h, g_wfc1_h);
    cudaGetSymbolAddress((void**)&wfc2_h, g_wfc2_h);

    const int SB = (int)GEMM_DYN;
    cudaFuncSetAttribute(gemm_kernel<192, 576, EPI_QKV>,  cudaFuncAttributeMaxDynamicSharedMemorySize, SB);
    cudaFuncSetAttribute(gemm_kernel<192, 192, EPI_PROJ>, cudaFuncAttributeMaxDynamicSharedMemorySize, SB);
    cudaFuncSetAttribute(gemm_kernel<192, 768, EPI_FC1>,  cudaFuncAttributeMaxDynamicSharedMemorySize, SB);
    cudaFuncSetAttribute(gemm_kernel<768, 192, EPI_FC2>,  cudaFuncAttributeMaxDynamicSharedMemorySize, SB);

    // 0. weight fp32 -> fp16
    f2h_kernel<<<(192 * 576 / 4 + 255) / 256, 256>>>(w_qkv,  wqkv_h,  192 * 576 / 4);
    f2h_kernel<<<(192 * 192 / 4 + 255) / 256, 256>>>(w_proj, wproj_h, 192 * 192 / 4);
    f2h_kernel<<<(192 * 768 / 4 + 255) / 256, 256>>>(w_fc1,  wfc1_h,  192 * 768 / 4);
    f2h_kernel<<<(768 * 192 / 4 + 255) / 256, 256>>>(w_fc2,  wfc2_h,  768 * 192 / 4);

    // 1. LN1 + window partition (fp16 out)
    ln_kernel<true><<<TOK / 8, 256>>>(x, g1, b1, ln);
    // 2. QKV GEMM: 3 column blocks of 192 (fp16 out)
    gemm_kernel<192, 576, EPI_QKV><<<dim3(3, TOK / GBM), 256, SB>>>(ln, wqkv_h, b_qkv, nullptr, big);
    // 3. attention per (window, head) (fp16 in/out)
    attn_kernel<<<dim3(6, 4096), 128>>>(big, ow);
    // 4. proj GEMM + window unpartition + residual x -> xo (fp32)
    gemm_kernel<192, 192, EPI_PROJ><<<dim3(1, TOK / GBM), 256, SB>>>(ow, wproj_h, b_proj, x, xo);
    // 5. LN2 (fp16 out)
    ln_kernel<false><<<TOK / 8, 256>>>(xo, g2, b2, ln);
    // 6. FC1 GEMM + exact GELU (fp16 out)
    gemm_kernel<192, 768, EPI_FC1><<<dim3(4, TOK / GBM), 256, SB>>>(ln, wfc1_h, b_fc1, nullptr, big);
    // 7. FC2 GEMM + residual xo -> out (fp32)
    gemm_kernel<768, 192, EPI_FC2><<<dim3(1, TOK / GBM), 256, SB>>>(big, wfc2_h, b_fc2, xo, out);
}

// round 6
// speedup vs baseline: 3.0498x; 1.1183x over previous
#include <cuda_runtime.h>
#include <cuda_fp16.h>
#include <mma.h>
#include <cstdint>

using namespace nvcuda;

#define TOK    262144          // 4*256*256 tokens
#define CDIM   192

// ---------------- scratch (device globals; no allocation) ----------------
__device__ __half g_ln  [(size_t)TOK * 192];   // LN1 (window layout) then LN2 (token layout)
__device__ __half g_big [(size_t)TOK * 768];   // qkv (576 wide) then fc1 activation (768 wide)
__device__ __half g_ow  [(size_t)TOK * 192];   // attention output, window layout
__device__ float  g_xo  [(size_t)TOK * 192];   // post-attention residual, token layout (fp32)
__device__ __half g_wqkv_h[192 * 576];
__device__ __half g_wproj_h[192 * 192];
__device__ __half g_wfc1_h[192 * 768];
__device__ __half g_wfc2_h[768 * 192];

// ---------------- cp.async helpers ----------------
__device__ __forceinline__ void cp_async16(void* smem_dst, const void* gmem_src) {
    uint32_t s = (uint32_t)__cvta_generic_to_shared(smem_dst);
    asm volatile("cp.async.cg.shared.global [%0], [%1], 16;\n" :: "r"(s), "l"(gmem_src));
}
__device__ __forceinline__ void cp_commit() {
    asm volatile("cp.async.commit_group;\n" ::: "memory");
}
template<int N>
__device__ __forceinline__ void cp_wait() {
    asm volatile("cp.async.wait_group %0;\n" :: "n"(N) : "memory");
}

// ---------------- fp32 -> fp16 weight conversion ----------------
__global__ __launch_bounds__(256) void f2h_kernel(const float* __restrict__ in,
                                                  __half* __restrict__ out, int n4)
{
    int i = blockIdx.x * 256 + threadIdx.x;
    if (i < n4) {
        float4 v = *(const float4*)(in + (size_t)i * 4);
        __half2 h0 = __floats2half2_rn(v.x, v.y);
        __half2 h1 = __floats2half2_rn(v.z, v.w);
        *(uint2*)(out + (size_t)i * 4) = make_uint2(*(uint32_t*)&h0, *(uint32_t*)&h1);
    }
}

// ---------------- LayerNorm (one warp per token), fp16 output ----------------
template<bool WINDOW_DST>
__global__ __launch_bounds__(256) void ln_kernel(const float* __restrict__ x,
                                                 const float* __restrict__ g,
                                                 const float* __restrict__ b,
                                                 __half* __restrict__ out)
{
    int tok  = blockIdx.x * (blockDim.x >> 5) + (threadIdx.x >> 5);
    int lane = threadIdx.x & 31;
    const float* row = x + (size_t)tok * CDIM;
    float v[6];
    float s = 0.f, s2 = 0.f;
#pragma unroll
    for (int k = 0; k < 6; k++) {
        v[k] = row[lane + 32 * k];
        s  += v[k];
        s2 += v[k] * v[k];
    }
#pragma unroll
    for (int o = 16; o > 0; o >>= 1) {
        s  += __shfl_xor_sync(0xffffffffu, s,  o);
        s2 += __shfl_xor_sync(0xffffffffu, s2, o);
    }
    float mean = s * (1.f / 192.f);
    float var  = s2 * (1.f / 192.f) - mean * mean;
    float inv  = rsqrtf(var + 1e-5f);

    size_t drow;
    if (WINDOW_DST) {
        int bb  = tok >> 16;
        int rem = tok & 65535;
        int h   = rem >> 8;
        int w   = rem & 255;
        int win = (bb << 10) + ((h >> 3) << 5) + (w >> 3);
        int n   = ((h & 7) << 3) + (w & 7);
        drow = (size_t)win * 64 + n;
    } else {
        drow = (size_t)tok;
    }
    __half* orow = out + drow * CDIM;
#pragma unroll
    for (int k = 0; k < 6; k++) {
        int c = lane + 32 * k;
        orow[c] = __float2half_rn((v[k] - mean) * inv * g[c] + b[c]);
    }
}

// ---------------- GEMM: fp16 wmma, 128x192 block, BK=64, cp.async 3-stage ----------------
#define GBM 128
#define GBN 192
#define GBK 64
#define NTHR 512

#define ALDH 72     // 64 + 8 halves pad
#define BLDH 200    // 192 + 8 halves pad
#define SA_HALF (GBM * ALDH)    // 9216 halves  = 18432 B
#define SB_HALF (GBK * BLDH)    // 12800 halves = 25600 B
#define STAGE_HALF (SA_HALF + SB_HALF)
#define PIPE_BYTES (3 * STAGE_HALF * 2)           // 132096 B
#define CLD 196
#define GEMM_DYN PIPE_BYTES     // epilogue fp32 tile 128*196*4 = 100352 < 132096

enum { EPI_QKV = 0, EPI_PROJ = 1, EPI_FC1 = 2, EPI_FC2 = 3 };

// A: [M][KDIM] half row-major; B: [KDIM][NDIM] half row-major.
template<int KDIM, int NDIM, int EPI>
__global__ __launch_bounds__(NTHR, 1) void gemm_kernel(const __half* __restrict__ A,
                                                       const __half* __restrict__ B,
                                                       const float* __restrict__ bias,
                                                       const float* __restrict__ res,
                                                       void* __restrict__ out_v)
{
    extern __shared__ char dynsm[];
    __half* sbase = (__half*)dynsm;
    float*  csm   = (float*)dynsm;

    const int bn   = blockIdx.x;
    const int bm   = blockIdx.y;
    const int tid  = threadIdx.x;
    const int warp = tid >> 5;
    const int wr   = warp >> 2;   // 0..3 : 32-row group
    const int wc   = warp & 3;    // 0..3 : 48-col group

    const __half* Abase = A + (size_t)(bm * GBM) * KDIM;
    const __half* Bbase = B + (size_t)bn * GBN;

    wmma::fragment<wmma::accumulator, 16, 16, 16, float> acc[2][3];
#pragma unroll
    for (int i = 0; i < 2; i++)
#pragma unroll
        for (int j = 0; j < 3; j++) wmma::fill_fragment(acc[i][j], 0.f);

    auto issue_stage = [&](int st, int k0) {
        __half* sa = sbase + st * STAGE_HALF;
        __half* sb = sa + SA_HALF;
        // A tile 128x64 halves: 1024 x 16B lines, 2/thread
#pragma unroll
        for (int s = 0; s < 2; s++) {
            int line = tid + s * NTHR;
            int r = line >> 3, c8 = line & 7;
            cp_async16(&sa[r * ALDH + c8 * 8],
                       Abase + (size_t)r * KDIM + k0 + c8 * 8);
        }
        // B tile 64x192 halves: 1536 x 16B lines, 3/thread
#pragma unroll
        for (int s = 0; s < 3; s++) {
            int line = tid + s * NTHR;
            int r = line / 24, c8 = line % 24;
            cp_async16(&sb[r * BLDH + c8 * 8],
                       Bbase + (size_t)(k0 + r) * NDIM + c8 * 8);
        }
        cp_commit();
    };

    constexpr int NK = KDIM / GBK;
    issue_stage(0, 0);
    if (NK > 1) issue_stage(1, GBK);

#pragma unroll 1
    for (int kt = 0; kt < NK; kt++) {
        const int cur = kt % 3;
        if (kt + 2 < NK) {
            issue_stage((kt + 2) % 3, (kt + 2) * GBK);
            cp_wait<2>();
        } else if (kt + 1 < NK) {
            cp_wait<1>();
        } else {
            cp_wait<0>();
        }
        __syncthreads();

        const __half* sa = sbase + cur * STAGE_HALF;
        const __half* sb = sa + SA_HALF;
#pragma unroll
        for (int kk = 0; kk < GBK; kk += 16) {
            wmma::fragment<wmma::matrix_a, 16, 16, 16, __half, wmma::row_major> af[2];
            wmma::fragment<wmma::matrix_b, 16, 16, 16, __half, wmma::row_major> bf[3];
#pragma unroll
            for (int i = 0; i < 2; i++)
                wmma::load_matrix_sync(af[i], &sa[(wr * 32 + i * 16) * ALDH + kk], ALDH);
#pragma unroll
            for (int j = 0; j < 3; j++)
                wmma::load_matrix_sync(bf[j], &sb[kk * BLDH + wc * 48 + j * 16], BLDH);
#pragma unroll
            for (int i = 0; i < 2; i++)
#pragma unroll
                for (int j = 0; j < 3; j++)
                    wmma::mma_sync(acc[i][j], af[i], bf[j], acc[i][j]);
        }
        __syncthreads();
    }

    // accumulators -> smem C tile (fp32), reusing pipeline smem
#pragma unroll
    for (int i = 0; i < 2; i++)
#pragma unroll
        for (int j = 0; j < 3; j++)
            wmma::store_matrix_sync(&csm[(wr * 32 + i * 16) * CLD + wc * 48 + j * 16],
                                    acc[i][j], CLD, wmma::mem_row_major);
    __syncthreads();

    // epilogue: 128x192 = 6144 float4-groups, 12 per thread
#pragma unroll
    for (int e = tid; e < GBM * (GBN / 4); e += NTHR) {
        int r  = e / 48;
        int c4 = e % 48;
        int gcol = bn * GBN + c4 * 4;
        size_t grow = (size_t)bm * GBM + r;
        float4 v  = *(float4*)&csm[r * CLD + c4 * 4];
        float4 bb = *(const float4*)&bias[gcol];
        v.x += bb.x; v.y += bb.y; v.z += bb.z; v.w += bb.w;

        if constexpr (EPI == EPI_QKV) {
            __half* out = (__half*)out_v;
            __half2 h0 = __floats2half2_rn(v.x, v.y);
            __half2 h1 = __floats2half2_rn(v.z, v.w);
            *(uint2*)&out[grow * NDIM + gcol] = make_uint2(*(uint32_t*)&h0, *(uint32_t*)&h1);
        } else if constexpr (EPI == EPI_PROJ) {
            float* out = (float*)out_v;
            int rg  = (int)grow;
            int win = rg >> 6, n = rg & 63;
            int bbi = win >> 10, wrw = win & 1023;
            int h   = ((wrw >> 5) << 3) + (n >> 3);
            int w   = ((wrw & 31) << 3) + (n & 7);
            size_t t = ((size_t)bbi << 16) + ((size_t)h << 8) + (size_t)w;
            float4 rr = *(const float4*)&res[t * CDIM + gcol];
            v.x += rr.x; v.y += rr.y; v.z += rr.z; v.w += rr.w;
            *(float4*)&out[t * CDIM + gcol] = v;
        } else if constexpr (EPI == EPI_FC1) {
            __half* out = (__half*)out_v;
            v.x *= normcdff(v.x); v.y *= normcdff(v.y);
            v.z *= normcdff(v.z); v.w *= normcdff(v.w);
            __half2 h0 = __floats2half2_rn(v.x, v.y);
            __half2 h1 = __floats2half2_rn(v.z, v.w);
            *(uint2*)&out[grow * NDIM + gcol] = make_uint2(*(uint32_t*)&h0, *(uint32_t*)&h1);
        } else {  // EPI_FC2
            float* out = (float*)out_v;
            float4 rr = *(const float4*)&res[grow * (size_t)CDIM + gcol];
            v.x += rr.x; v.y += rr.y; v.z += rr.z; v.w += rr.w;
            *(float4*)&out[grow * (size_t)NDIM + gcol] = v;
        }
    }
}

// ---------------- attention: one block per (window, head), fp32 math, fp16 I/O ----------------
__global__ __launch_bounds__(128) void attn_kernel(const __half* __restrict__ qkv,
                                                   __half* __restrict__ o)
{
    __shared__ float qs[64][36];
    __shared__ float ks[64][32];
    __shared__ float vs[64][32];
    __shared__ float ps[64][68];

    const int head = blockIdx.x;     // 0..5
    const int win  = blockIdx.y;     // 0..4095
    const int tid  = threadIdx.x;

    const __half* base = qkv + (size_t)win * 64 * 576 + head * 32;

#pragma unroll
    for (int t = 0; t < 2; t++) {
        int idx = tid + t * 128;           // 0..255
        int r = idx >> 2, c8 = idx & 3;
        const __half* rp = base + (size_t)r * 576;
#pragma unroll
        for (int which = 0; which < 3; which++) {
            const __half* src = rp + which * 192 + c8 * 8;
            uint2 raw = *(const uint2*)src;
            __half2 h0 = *(__half2*)&raw.x;
            __half2 h1 = *(__half2*)&raw.y;
            uint2 raw2 = *(const uint2*)(src + 4);
            __half2 h2 = *(__half2*)&raw2.x;
            __half2 h3 = *(__half2*)&raw2.y;
            float* dst = (which == 0) ? &qs[r][c8 * 8] : (which == 1) ? &ks[r][c8 * 8] : &vs[r][c8 * 8];
            float2 f0 = __half22float2(h0), f1 = __half22float2(h1);
            float2 f2 = __half22float2(h2), f3 = __half22float2(h3);
            dst[0] = f0.x; dst[1] = f0.y; dst[2] = f1.x; dst[3] = f1.y;
            dst[4] = f2.x; dst[5] = f2.y; dst[6] = f3.x; dst[7] = f3.y;
        }
    }
    __syncthreads();

    const int i    = tid >> 1;
    const int half = tid & 1;
    const int j0   = half * 32;

    float qr[32];
#pragma unroll
    for (int c4 = 0; c4 < 8; c4++)
        *(float4*)&qr[c4 * 4] = *(float4*)&qs[i][c4 * 4];

    float sv[32];
#pragma unroll
    for (int jj = 0; jj < 32; jj++) {
        int j = j0 + jj;
        float a = 0.f;
#pragma unroll
        for (int c4 = 0; c4 < 8; c4++) {
            float4 kv = *(float4*)&ks[j][c4 * 4];
            a += qr[c4 * 4 + 0] * kv.x;
            a += qr[c4 * 4 + 1] * kv.y;
            a += qr[c4 * 4 + 2] * kv.z;
            a += qr[c4 * 4 + 3] * kv.w;
        }
        sv[jj] = a * 0.17677669529663687f;
    }

    float m = -1e30f;
#pragma unroll
    for (int jj = 0; jj < 32; jj++) m = fmaxf(m, sv[jj]);
    m = fmaxf(m, __shfl_xor_sync(0xffffffffu, m, 1));
    float sum = 0.f;
#pragma unroll
    for (int jj = 0; jj < 32; jj++) { sv[jj] = __expf(sv[jj] - m); sum += sv[jj]; }
    sum += __shfl_xor_sync(0xffffffffu, sum, 1);
    float rinv = 1.f / sum;
#pragma unroll
    for (int c4 = 0; c4 < 8; c4++) {
        float4 p = make_float4(sv[c4 * 4] * rinv, sv[c4 * 4 + 1] * rinv,
                               sv[c4 * 4 + 2] * rinv, sv[c4 * 4 + 3] * rinv);
        *(float4*)&ps[i][j0 + c4 * 4] = p;
    }
    __syncwarp();

    float oacc[16];
#pragma unroll
    for (int t = 0; t < 16; t++) oacc[t] = 0.f;
#pragma unroll
    for (int j = 0; j < 64; j++) {
        float p = ps[i][j];
#pragma unroll
        for (int c4 = 0; c4 < 4; c4++) {
            float4 vv = *(float4*)&vs[j][half * 16 + c4 * 4];
            oacc[c4 * 4 + 0] += p * vv.x;
            oacc[c4 * 4 + 1] += p * vv.y;
            oacc[c4 * 4 + 2] += p * vv.z;
            oacc[c4 * 4 + 3] += p * vv.w;
        }
    }
    __half* orow = o + (size_t)(win * 64 + i) * CDIM + head * 32 + half * 16;
#pragma unroll
    for (int c4 = 0; c4 < 4; c4++) {
        __half2 h0 = __floats2half2_rn(oacc[c4 * 4 + 0], oacc[c4 * 4 + 1]);
        __half2 h1 = __floats2half2_rn(oacc[c4 * 4 + 2], oacc[c4 * 4 + 3]);
        *(uint2*)&orow[c4 * 4] = make_uint2(*(uint32_t*)&h0, *(uint32_t*)&h1);
    }
}

// ---------------- launch ----------------
extern "C" void kernel_launch(void* const* d_in, const int* in_sizes, int n_in,
                              void* d_out, int out_size)
{
    (void)in_sizes; (void)n_in; (void)out_size;
    const float* x      = (const float*)d_in[0];
    const float* g1     = (const float*)d_in[1];
    const float* b1     = (const float*)d_in[2];
    const float* w_qkv  = (const float*)d_in[3];
    const float* b_qkv  = (const float*)d_in[4];
    const float* w_proj = (const float*)d_in[5];
    const float* b_proj = (const float*)d_in[6];
    const float* g2     = (const float*)d_in[7];
    const float* b2     = (const float*)d_in[8];
    const float* w_fc1  = (const float*)d_in[9];
    const float* b_fc1  = (const float*)d_in[10];
    const float* w_fc2  = (const float*)d_in[11];
    const float* b_fc2  = (const float*)d_in[12];
    float* out = (float*)d_out;

    __half *ln, *big, *ow, *wqkv_h, *wproj_h, *wfc1_h, *wfc2_h;
    float *xo;
    cudaGetSymbolAddress((void**)&ln,  g_ln);
    cudaGetSymbolAddress((void**)&big, g_big);
    cudaGetSymbolAddress((void**)&ow,  g_ow);
    cudaGetSymbolAddress((void**)&xo,  g_xo);
    cudaGetSymbolAddress((void**)&wqkv_h, g_wqkv_h);
    cudaGetSymbolAddress((void**)&wproj_h, g_wproj_h);
    cudaGetSymbolAddress((void**)&wfc1_h, g_wfc1_h);
    cudaGetSymbolAddress((void**)&wfc2_h, g_wfc2_h);

    const int SB = (int)GEMM_DYN;
    cudaFuncSetAttribute(gemm_kernel<192, 576, EPI_QKV>,  cudaFuncAttributeMaxDynamicSharedMemorySize, SB);
    cudaFuncSetAttribute(gemm_kernel<192, 192, EPI_PROJ>, cudaFuncAttributeMaxDynamicSharedMemorySize, SB);
    cudaFuncSetAttribute(gemm_kernel<192, 768, EPI_FC1>,  cudaFuncAttributeMaxDynamicSharedMemorySize, SB);
    cudaFuncSetAttribute(gemm_kernel<768, 192, EPI_FC2>,  cudaFuncAttributeMaxDynamicSharedMemorySize, SB);

    // 0. weight fp32 -> fp16
    f2h_kernel<<<(192 * 576 / 4 + 255) / 256, 256>>>(w_qkv,  wqkv_h,  192 * 576 / 4);
    f2h_kernel<<<(192 * 192 / 4 + 255) / 256, 256>>>(w_proj, wproj_h, 192 * 192 / 4);
    f2h_kernel<<<(192 * 768 / 4 + 255) / 256, 256>>>(w_fc1,  wfc1_h,  192 * 768 / 4);
    f2h_kernel<<<(768 * 192 / 4 + 255) / 256, 256>>>(w_fc2,  wfc2_h,  768 * 192 / 4);

    // 1. LN1 + window partition (fp16 out)
    ln_kernel<true><<<TOK / 8, 256>>>(x, g1, b1, ln);
    // 2. QKV GEMM: 3 column blocks of 192 (fp16 out)
    gemm_kernel<192, 576, EPI_QKV><<<dim3(3, TOK / GBM), NTHR, SB>>>(ln, wqkv_h, b_qkv, nullptr, big);
    // 3. attention per (window, head) (fp16 in/out)
    attn_kernel<<<dim3(6, 4096), 128>>>(big, ow);
    // 4. proj GEMM + window unpartition + residual x -> xo (fp32)
    gemm_kernel<192, 192, EPI_PROJ><<<dim3(1, TOK / GBM), NTHR, SB>>>(ow, wproj_h, b_proj, x, xo);
    // 5. LN2 (fp16 out)
    ln_kernel<false><<<TOK / 8, 256>>>(xo, g2, b2, ln);
    // 6. FC1 GEMM + exact GELU (fp16 out)
    gemm_kernel<192, 768, EPI_FC1><<<dim3(4, TOK / GBM), NTHR, SB>>>(ln, wfc1_h, b_fc1, nullptr, big);
    // 7. FC2 GEMM + residual xo -> out (fp32)
    gemm_kernel<768, 192, EPI_FC2><<<dim3(1, TOK / GBM), NTHR, SB>>>(big, wfc2_h, b_fc2, xo, out);
}

// round 7
// speedup vs baseline: 3.7739x; 1.2374x over previous
#include <cuda_runtime.h>
#include <cuda_fp16.h>
#include <mma.h>
#include <cstdint>

using namespace nvcuda;

#define TOK    262144          // 4*256*256 tokens
#define CDIM   192

// ---------------- scratch (device globals; no allocation) ----------------
__device__ __half g_ln  [(size_t)TOK * 192];   // LN1 (window layout) then LN2 (token layout)
__device__ __half g_big [(size_t)TOK * 768];   // qkv (576 wide) then fc1 activation (768 wide)
__device__ __half g_ow  [(size_t)TOK * 192];   // attention output, window layout
__device__ float  g_xo  [(size_t)TOK * 192];   // post-attention residual, token layout (fp32)
__device__ __half g_wqkv_h[192 * 576];
__device__ __half g_wproj_h[192 * 192];
__device__ __half g_wfc1_h[192 * 768];
__device__ __half g_wfc2_h[768 * 192];

// ---------------- cp.async helpers ----------------
__device__ __forceinline__ void cp_async16(void* smem_dst, const void* gmem_src) {
    uint32_t s = (uint32_t)__cvta_generic_to_shared(smem_dst);
    asm volatile("cp.async.cg.shared.global [%0], [%1], 16;\n" :: "r"(s), "l"(gmem_src));
}
__device__ __forceinline__ void cp_commit() {
    asm volatile("cp.async.commit_group;\n" ::: "memory");
}
template<int N>
__device__ __forceinline__ void cp_wait() {
    asm volatile("cp.async.wait_group %0;\n" :: "n"(N) : "memory");
}

// ---------------- fp32 -> fp16 weight conversion ----------------
__global__ __launch_bounds__(256) void f2h_kernel(const float* __restrict__ in,
                                                  __half* __restrict__ out, int n4)
{
    int i = blockIdx.x * 256 + threadIdx.x;
    if (i < n4) {
        float4 v = *(const float4*)(in + (size_t)i * 4);
        __half2 h0 = __floats2half2_rn(v.x, v.y);
        __half2 h1 = __floats2half2_rn(v.z, v.w);
        *(uint2*)(out + (size_t)i * 4) = make_uint2(*(uint32_t*)&h0, *(uint32_t*)&h1);
    }
}

// ---------------- LayerNorm (one warp per token), fp16 output ----------------
template<bool WINDOW_DST>
__global__ __launch_bounds__(256) void ln_kernel(const float* __restrict__ x,
                                                 const float* __restrict__ g,
                                                 const float* __restrict__ b,
                                                 __half* __restrict__ out)
{
    int tok  = blockIdx.x * (blockDim.x >> 5) + (threadIdx.x >> 5);
    int lane = threadIdx.x & 31;
    const float* row = x + (size_t)tok * CDIM;
    float v[6];
    float s = 0.f, s2 = 0.f;
#pragma unroll
    for (int k = 0; k < 6; k++) {
        v[k] = row[lane + 32 * k];
        s  += v[k];
        s2 += v[k] * v[k];
    }
#pragma unroll
    for (int o = 16; o > 0; o >>= 1) {
        s  += __shfl_xor_sync(0xffffffffu, s,  o);
        s2 += __shfl_xor_sync(0xffffffffu, s2, o);
    }
    float mean = s * (1.f / 192.f);
    float var  = s2 * (1.f / 192.f) - mean * mean;
    float inv  = rsqrtf(var + 1e-5f);

    size_t drow;
    if (WINDOW_DST) {
        int bb  = tok >> 16;
        int rem = tok & 65535;
        int h   = rem >> 8;
        int w   = rem & 255;
        int win = (bb << 10) + ((h >> 3) << 5) + (w >> 3);
        int n   = ((h & 7) << 3) + (w & 7);
        drow = (size_t)win * 64 + n;
    } else {
        drow = (size_t)tok;
    }
    __half* orow = out + drow * CDIM;
#pragma unroll
    for (int k = 0; k < 6; k++) {
        int c = lane + 32 * k;
        orow[c] = __float2half_rn((v[k] - mean) * inv * g[c] + b[c]);
    }
}

// ---------------- GEMM: fp16 wmma, 128x192 block, BK=64, cp.async 3-stage ----------------
#define GBM 128
#define GBN 192
#define GBK 64
#define NTHR 512

#define ALDH 72     // 64 + 8 halves pad
#define BLDH 200    // 192 + 8 halves pad
#define SA_HALF (GBM * ALDH)    // 9216 halves  = 18432 B
#define SB_HALF (GBK * BLDH)    // 12800 halves = 25600 B
#define STAGE_HALF (SA_HALF + SB_HALF)
#define PIPE_BYTES (3 * STAGE_HALF * 2)           // 132096 B
#define CLD 196
#define GEMM_DYN PIPE_BYTES     // epilogue fp32 tile 128*196*4 = 100352 < 132096

enum { EPI_QKV = 0, EPI_PROJ = 1, EPI_FC1 = 2, EPI_FC2 = 3 };

// A: [M][KDIM] half row-major; B: [KDIM][NDIM] half row-major.
template<int KDIM, int NDIM, int EPI>
__global__ __launch_bounds__(NTHR, 1) void gemm_kernel(const __half* __restrict__ A,
                                                       const __half* __restrict__ B,
                                                       const float* __restrict__ bias,
                                                       const float* __restrict__ res,
                                                       void* __restrict__ out_v)
{
    extern __shared__ char dynsm[];
    __half* sbase = (__half*)dynsm;
    float*  csm   = (float*)dynsm;

    const int bn   = blockIdx.x;
    const int bm   = blockIdx.y;
    const int tid  = threadIdx.x;
    const int warp = tid >> 5;
    const int wr   = warp >> 2;   // 0..3 : 32-row group
    const int wc   = warp & 3;    // 0..3 : 48-col group

    const __half* Abase = A + (size_t)(bm * GBM) * KDIM;
    const __half* Bbase = B + (size_t)bn * GBN;

    wmma::fragment<wmma::accumulator, 16, 16, 16, float> acc[2][3];
#pragma unroll
    for (int i = 0; i < 2; i++)
#pragma unroll
        for (int j = 0; j < 3; j++) wmma::fill_fragment(acc[i][j], 0.f);

    auto issue_stage = [&](int st, int k0) {
        __half* sa = sbase + st * STAGE_HALF;
        __half* sb = sa + SA_HALF;
        // A tile 128x64 halves: 1024 x 16B lines, 2/thread
#pragma unroll
        for (int s = 0; s < 2; s++) {
            int line = tid + s * NTHR;
            int r = line >> 3, c8 = line & 7;
            cp_async16(&sa[r * ALDH + c8 * 8],
                       Abase + (size_t)r * KDIM + k0 + c8 * 8);
        }
        // B tile 64x192 halves: 1536 x 16B lines, 3/thread
#pragma unroll
        for (int s = 0; s < 3; s++) {
            int line = tid + s * NTHR;
            int r = line / 24, c8 = line % 24;
            cp_async16(&sb[r * BLDH + c8 * 8],
                       Bbase + (size_t)(k0 + r) * NDIM + c8 * 8);
        }
        cp_commit();
    };

    constexpr int NK = KDIM / GBK;
    issue_stage(0, 0);
    if (NK > 1) issue_stage(1, GBK);

    // Single-barrier mainloop: wait(cur ready) -> barrier -> issue(kt+2) -> compute(kt).
    // The barrier at iter kt guarantees all warps finished compute(kt-1), whose buffer
    // ((kt-1)%3 == (kt+2)%3) is the one issue overwrites.
#pragma unroll 1
    for (int kt = 0; kt < NK; kt++) {
        if (kt + 1 < NK) cp_wait<1>(); else cp_wait<0>();
        __syncthreads();
        if (kt + 2 < NK) issue_stage((kt + 2) % 3, (kt + 2) * GBK);

        const __half* sa = sbase + (kt % 3) * STAGE_HALF;
        const __half* sb = sa + SA_HALF;
#pragma unroll
        for (int kk = 0; kk < GBK; kk += 16) {
            wmma::fragment<wmma::matrix_a, 16, 16, 16, __half, wmma::row_major> af[2];
            wmma::fragment<wmma::matrix_b, 16, 16, 16, __half, wmma::row_major> bf[3];
#pragma unroll
            for (int i = 0; i < 2; i++)
                wmma::load_matrix_sync(af[i], &sa[(wr * 32 + i * 16) * ALDH + kk], ALDH);
#pragma unroll
            for (int j = 0; j < 3; j++)
                wmma::load_matrix_sync(bf[j], &sb[kk * BLDH + wc * 48 + j * 16], BLDH);
#pragma unroll
            for (int i = 0; i < 2; i++)
#pragma unroll
                for (int j = 0; j < 3; j++)
                    wmma::mma_sync(acc[i][j], af[i], bf[j], acc[i][j]);
        }
    }
    __syncthreads();   // all compute done before csm overwrites stage buffers

    // accumulators -> smem C tile (fp32), reusing pipeline smem
#pragma unroll
    for (int i = 0; i < 2; i++)
#pragma unroll
        for (int j = 0; j < 3; j++)
            wmma::store_matrix_sync(&csm[(wr * 32 + i * 16) * CLD + wc * 48 + j * 16],
                                    acc[i][j], CLD, wmma::mem_row_major);
    __syncthreads();

    // epilogue: 128x192 = 6144 float4-groups, 12 per thread
#pragma unroll
    for (int e = tid; e < GBM * (GBN / 4); e += NTHR) {
        int r  = e / 48;
        int c4 = e % 48;
        int gcol = bn * GBN + c4 * 4;
        size_t grow = (size_t)bm * GBM + r;
        float4 v  = *(float4*)&csm[r * CLD + c4 * 4];
        float4 bb = *(const float4*)&bias[gcol];
        v.x += bb.x; v.y += bb.y; v.z += bb.z; v.w += bb.w;

        if constexpr (EPI == EPI_QKV) {
            __half* out = (__half*)out_v;
            __half2 h0 = __floats2half2_rn(v.x, v.y);
            __half2 h1 = __floats2half2_rn(v.z, v.w);
            *(uint2*)&out[grow * NDIM + gcol] = make_uint2(*(uint32_t*)&h0, *(uint32_t*)&h1);
        } else if constexpr (EPI == EPI_PROJ) {
            float* out = (float*)out_v;
            int rg  = (int)grow;
            int win = rg >> 6, n = rg & 63;
            int bbi = win >> 10, wrw = win & 1023;
            int h   = ((wrw >> 5) << 3) + (n >> 3);
            int w   = ((wrw & 31) << 3) + (n & 7);
            size_t t = ((size_t)bbi << 16) + ((size_t)h << 8) + (size_t)w;
            float4 rr = *(const float4*)&res[t * CDIM + gcol];
            v.x += rr.x; v.y += rr.y; v.z += rr.z; v.w += rr.w;
            *(float4*)&out[t * CDIM + gcol] = v;
        } else if constexpr (EPI == EPI_FC1) {
            __half* out = (__half*)out_v;
            v.x *= normcdff(v.x); v.y *= normcdff(v.y);
            v.z *= normcdff(v.z); v.w *= normcdff(v.w);
            __half2 h0 = __floats2half2_rn(v.x, v.y);
            __half2 h1 = __floats2half2_rn(v.z, v.w);
            *(uint2*)&out[grow * NDIM + gcol] = make_uint2(*(uint32_t*)&h0, *(uint32_t*)&h1);
        } else {  // EPI_FC2
            float* out = (float*)out_v;
            float4 rr = *(const float4*)&res[grow * (size_t)CDIM + gcol];
            v.x += rr.x; v.y += rr.y; v.z += rr.z; v.w += rr.w;
            *(float4*)&out[grow * (size_t)NDIM + gcol] = v;
        }
    }
}

// ---------------- attention: wmma, one block per (window, head-pair) ----------------
// grid (3, 4096), 256 threads (8 warps). Heads 2*hp, 2*hp+1.
#define AQLD 72    // half ld for q/k/v/p tiles (64+8)
#define ASLD 68    // float ld for S tiles
#define ATTN_DYN (3 * 64 * AQLD * 2 + 2 * 64 * ASLD * 4 + 2 * 64 * AQLD * 2)  // 80896 B

__global__ __launch_bounds__(256) void attn_kernel(const __half* __restrict__ qkv,
                                                   __half* __restrict__ o)
{
    extern __shared__ char smraw[];
    __half* qs  = (__half*)smraw;
    __half* ks  = qs + 64 * AQLD;
    __half* vs  = ks + 64 * AQLD;
    float*  ss0 = (float*)(vs + 64 * AQLD);
    float*  ss1 = ss0 + 64 * ASLD;
    __half* ps0 = (__half*)(ss1 + 64 * ASLD);
    __half* ps1 = ps0 + 64 * AQLD;

    const int hp  = blockIdx.x;      // head pair 0..2
    const int win = blockIdx.y;      // 0..4095
    const int tid = threadIdx.x;
    const int wid = tid >> 5;

    // load q,k,v: 64 rows x 64 halves (two heads) each
    const __half* base = qkv + (size_t)win * 36864 + hp * 64;
#pragma unroll
    for (int s = 0; s < 2; s++) {
        int idx = tid + s * 256;
        int r = idx >> 3, c8 = idx & 7;
        const __half* rp = base + (size_t)r * 576 + c8 * 8;
        *(uint4*)&qs[r * AQLD + c8 * 8] = *(const uint4*)(rp);
        *(uint4*)&ks[r * AQLD + c8 * 8] = *(const uint4*)(rp + 192);
        *(uint4*)&vs[r * AQLD + c8 * 8] = *(const uint4*)(rp + 384);
    }
    __syncthreads();

    const int hh    = wid >> 2;   // head within pair
    const int strip = wid & 3;    // 16-row strip
    float*  ssh = hh ? ss1 : ss0;
    __half* psh = hh ? ps1 : ps0;

    // S = Q K^T  (warp: rows strip*16..+15, all 64 cols)
    {
        wmma::fragment<wmma::accumulator, 16, 16, 16, float> acc[4];
#pragma unroll
        for (int t = 0; t < 4; t++) wmma::fill_fragment(acc[t], 0.f);
#pragma unroll
        for (int k0 = 0; k0 < 32; k0 += 16) {
            wmma::fragment<wmma::matrix_a, 16, 16, 16, __half, wmma::row_major> af;
            wmma::load_matrix_sync(af, &qs[strip * 16 * AQLD + hh * 32 + k0], AQLD);
#pragma unroll
            for (int tn = 0; tn < 4; tn++) {
                // B[k][n] = K[n][k] -> col_major view of ks rows
                wmma::fragment<wmma::matrix_b, 16, 16, 16, __half, wmma::col_major> bf;
                wmma::load_matrix_sync(bf, &ks[tn * 16 * AQLD + hh * 32 + k0], AQLD);
                wmma::mma_sync(acc[tn], af, bf, acc[tn]);
            }
        }
#pragma unroll
        for (int tn = 0; tn < 4; tn++)
            wmma::store_matrix_sync(&ssh[strip * 16 * ASLD + tn * 16], acc[tn], ASLD,
                                    wmma::mem_row_major);
    }
    __syncthreads();

    // softmax: thread pair per row (2 heads x 64 rows x 2 halves = 256)
    {
        const int head = tid >> 7;
        const int i    = (tid >> 1) & 63;
        const int half = tid & 1;
        const int j0   = half * 32;
        float* srow = (head ? ss1 : ss0) + i * ASLD + j0;
        float sv[32];
        float m = -1e30f;
#pragma unroll
        for (int jj = 0; jj < 32; jj++) {
            sv[jj] = srow[jj] * 0.17677669529663687f;
            m = fmaxf(m, sv[jj]);
        }
        m = fmaxf(m, __shfl_xor_sync(0xffffffffu, m, 1));
        float sum = 0.f;
#pragma unroll
        for (int jj = 0; jj < 32; jj++) { sv[jj] = __expf(sv[jj] - m); sum += sv[jj]; }
        sum += __shfl_xor_sync(0xffffffffu, sum, 1);
        float rinv = 1.f / sum;
        __half* prow = (head ? ps1 : ps0) + i * AQLD + j0;
#pragma unroll
        for (int jj = 0; jj < 16; jj++) {
            __half2 h = __floats2half2_rn(sv[jj * 2] * rinv, sv[jj * 2 + 1] * rinv);
            *(__half2*)&prow[jj * 2] = h;
        }
    }
    __syncthreads();

    // O = P V  (warp: rows strip*16..+15, 32 head dims)
    {
        wmma::fragment<wmma::accumulator, 16, 16, 16, float> acc[2];
#pragma unroll
        for (int t = 0; t < 2; t++) wmma::fill_fragment(acc[t], 0.f);
#pragma unroll
        for (int k0 = 0; k0 < 64; k0 += 16) {
            wmma::fragment<wmma::matrix_a, 16, 16, 16, __half, wmma::row_major> af;
            wmma::load_matrix_sync(af, &psh[strip * 16 * AQLD + k0], AQLD);
#pragma unroll
            for (int tn = 0; tn < 2; tn++) {
                wmma::fragment<wmma::matrix_b, 16, 16, 16, __half, wmma::row_major> bf;
                wmma::load_matrix_sync(bf, &vs[k0 * AQLD + hh * 32 + tn * 16], AQLD);
                wmma::mma_sync(acc[tn], af, bf, acc[tn]);
            }
        }
#pragma unroll
        for (int tn = 0; tn < 2; tn++)
            wmma::store_matrix_sync(&ssh[strip * 16 * 36 + tn * 16], acc[tn], 36,
                                    wmma::mem_row_major);
    }
    __syncthreads();

    // write O: 2 heads x 64 rows x 32 cols fp16
    {
        const int head = tid >> 7;
        const int r    = tid & 63;
        const int hf   = (tid >> 6) & 1;
        const int c0   = hf * 16;
        float* srow = (head ? ss1 : ss0) + r * 36 + c0;
        __half* orow = o + (size_t)(win * 64 + r) * 192 + hp * 64 + head * 32 + c0;
        uint4 pack[2];
#pragma unroll
        for (int q = 0; q < 2; q++) {
            float4 a = *(float4*)&srow[q * 8];
            float4 b = *(float4*)&srow[q * 8 + 4];
            __half2 h0 = __floats2half2_rn(a.x, a.y);
            __half2 h1 = __floats2half2_rn(a.z, a.w);
            __half2 h2 = __floats2half2_rn(b.x, b.y);
            __half2 h3 = __floats2half2_rn(b.z, b.w);
            pack[q] = make_uint4(*(uint32_t*)&h0, *(uint32_t*)&h1,
                                 *(uint32_t*)&h2, *(uint32_t*)&h3);
        }
        *(uint4*)&orow[0] = pack[0];
        *(uint4*)&orow[8] = pack[1];
    }
}

// ---------------- launch ----------------
extern "C" void kernel_launch(void* const* d_in, const int* in_sizes, int n_in,
                              void* d_out, int out_size)
{
    (void)in_sizes; (void)n_in; (void)out_size;
    const float* x      = (const float*)d_in[0];
    const float* g1     = (const float*)d_in[1];
    const float* b1     = (const float*)d_in[2];
    const float* w_qkv  = (const float*)d_in[3];
    const float* b_qkv  = (const float*)d_in[4];
    const float* w_proj = (const float*)d_in[5];
    const float* b_proj = (const float*)d_in[6];
    const float* g2     = (const float*)d_in[7];
    const float* b2     = (const float*)d_in[8];
    const float* w_fc1  = (const float*)d_in[9];
    const float* b_fc1  = (const float*)d_in[10];
    const float* w_fc2  = (const float*)d_in[11];
    const float* b_fc2  = (const float*)d_in[12];
    float* out = (float*)d_out;

    __half *ln, *big, *ow, *wqkv_h, *wproj_h, *wfc1_h, *wfc2_h;
    float *xo;
    cudaGetSymbolAddress((void**)&ln,  g_ln);
    cudaGetSymbolAddress((void**)&big, g_big);
    cudaGetSymbolAddress((void**)&ow,  g_ow);
    cudaGetSymbolAddress((void**)&xo,  g_xo);
    cudaGetSymbolAddress((void**)&wqkv_h, g_wqkv_h);
    cudaGetSymbolAddress((void**)&wproj_h, g_wproj_h);
    cudaGetSymbolAddress((void**)&wfc1_h, g_wfc1_h);
    cudaGetSymbolAddress((void**)&wfc2_h, g_wfc2_h);

    const int SB = (int)GEMM_DYN;
    cudaFuncSetAttribute(gemm_kernel<192, 576, EPI_QKV>,  cudaFuncAttributeMaxDynamicSharedMemorySize, SB);
    cudaFuncSetAttribute(gemm_kernel<192, 192, EPI_PROJ>, cudaFuncAttributeMaxDynamicSharedMemorySize, SB);
    cudaFuncSetAttribute(gemm_kernel<192, 768, EPI_FC1>,  cudaFuncAttributeMaxDynamicSharedMemorySize, SB);
    cudaFuncSetAttribute(gemm_kernel<768, 192, EPI_FC2>,  cudaFuncAttributeMaxDynamicSharedMemorySize, SB);
    cudaFuncSetAttribute(attn_kernel, cudaFuncAttributeMaxDynamicSharedMemorySize, ATTN_DYN);

    // 0. weight fp32 -> fp16
    f2h_kernel<<<(192 * 576 / 4 + 255) / 256, 256>>>(w_qkv,  wqkv_h,  192 * 576 / 4);
    f2h_kernel<<<(192 * 192 / 4 + 255) / 256, 256>>>(w_proj, wproj_h, 192 * 192 / 4);
    f2h_kernel<<<(192 * 768 / 4 + 255) / 256, 256>>>(w_fc1,  wfc1_h,  192 * 768 / 4);
    f2h_kernel<<<(768 * 192 / 4 + 255) / 256, 256>>>(w_fc2,  wfc2_h,  768 * 192 / 4);

    // 1. LN1 + window partition (fp16 out)
    ln_kernel<true><<<TOK / 8, 256>>>(x, g1, b1, ln);
    // 2. QKV GEMM: 3 column blocks of 192 (fp16 out)
    gemm_kernel<192, 576, EPI_QKV><<<dim3(3, TOK / GBM), NTHR, SB>>>(ln, wqkv_h, b_qkv, nullptr, big);
    // 3. attention per (window, head-pair) (wmma)
    attn_kernel<<<dim3(3, 4096), 256, ATTN_DYN>>>(big, ow);
    // 4. proj GEMM + window unpartition + residual x -> xo (fp32)
    gemm_kernel<192, 192, EPI_PROJ><<<dim3(1, TOK / GBM), NTHR, SB>>>(ow, wproj_h, b_proj, x, xo);
    // 5. LN2 (fp16 out)
    ln_kernel<false><<<TOK / 8, 256>>>(xo, g2, b2, ln);
    // 6. FC1 GEMM + exact GELU (fp16 out)
    gemm_kernel<192, 768, EPI_FC1><<<dim3(4, TOK / GBM), NTHR, SB>>>(ln, wfc1_h, b_fc1, nullptr, big);
    // 7. FC2 GEMM + residual xo -> out (fp32)
    gemm_kernel<768, 192, EPI_FC2><<<dim3(1, TOK / GBM), NTHR, SB>>>(big, wfc2_h, b_fc2, xo, out);
}